// round 5
// baseline (speedup 1.0000x reference)
#include <cuda_runtime.h>
#include <cuda_bf16.h>
#include <math.h>
#include <stdint.h>

#define D       512
#define NTOK    4096      // B*SLEN = 4*1024
#define NNODn   8
#define NEDGEn  34
#define EPSf    1e-6f

// GEMM tile
#define BM 128
#define BN 64
#define BK 32        // k per stage (16 k2-pairs)
#define BK2 16

// ---------------- scratch buffers (device globals; no allocation allowed) ----------
__device__ float g_outs[8][NTOK * D];
__device__ float g_q[NTOK * D];
__device__ float g_k[NTOK * D];
__device__ float g_v[NTOK * D];
__device__ float g_t1[NTOK * D];
__device__ float g_t2[NTOK * D];
__device__ float g_t3[NTOK * D];
__device__ float g_t4[NTOK * D];

// pre-split operand buffers: {hi bf16x2, lo bf16x2} per k-pair
__device__ uint2 g_Ac[NTOK * 256];                 // [m][k2]
__device__ uint2 g_Wc[56 * 512 * 256];             // [slot][n][k2]

// ---------------- descriptors ----------------
struct GemmDesc {
    int active;
    int pre_mode;    // 0 none, 1 LN(A), 2 relu(A)
    int epi_act;     // 0 none, 1 relu, 2 gelu
    int accumulate;  // 1: C += result
    const float *A, *W, *bias, *lng, *lnb, *mult, *residual;
    float scale;
    float *C;
};
struct CopyDesc { int active; const float* src; float* dst; float scale; };
struct ElemDesc {
    int active; int opcode;   // 2,4,6,7
    const float *q, *k, *v, *g, *b;
    float scale; float* dst;
};

__device__ GemmDesc g_gd[56];   // node*7 + {EQ,EK,EV,G1,G2,G3,G4}
__device__ CopyDesc g_cd[24];   // node*3 + {q,k,v}
__device__ ElemDesc g_ed[8];
__device__ int g_attn_on[8];
__device__ int g_rem_mask;

// ---------------- bf16 split helpers ----------------
__device__ __forceinline__ uint2 split_pair(float x0, float x1) {
    __nv_bfloat16 h0 = __float2bfloat16_rn(x0);
    __nv_bfloat16 h1 = __float2bfloat16_rn(x1);
    __nv_bfloat16 l0 = __float2bfloat16_rn(x0 - __bfloat162float(h0));
    __nv_bfloat16 l1 = __float2bfloat16_rn(x1 - __bfloat162float(h1));
    __nv_bfloat162 hh = __halves2bfloat162(h0, h1);   // .x = low = even k
    __nv_bfloat162 ll = __halves2bfloat162(l0, l1);
    uint2 r;
    r.x = *(uint32_t*)&hh;
    r.y = *(uint32_t*)&ll;
    return r;
}

__device__ __forceinline__ void mma_bf16(float* c, const uint32_t* a, const uint32_t* b) {
    asm volatile(
        "mma.sync.aligned.m16n8k16.row.col.f32.bf16.bf16.f32 "
        "{%0,%1,%2,%3}, {%4,%5,%6,%7}, {%8,%9}, {%0,%1,%2,%3};"
        : "+f"(c[0]), "+f"(c[1]), "+f"(c[2]), "+f"(c[3])
        : "r"(a[0]), "r"(a[1]), "r"(a[2]), "r"(a[3]),
          "r"(b[0]), "r"(b[1]));
}

// ---------------- small helpers ----------------
__device__ __forceinline__ float gelu_f(float x) {
    const float k0 = 0.7978845608028654f;
    float x3 = x * x * x;
    return 0.5f * x * (1.f + tanhf(k0 * (x + 0.044715f * x3)));
}

__device__ float selw_masked(const float* l, int L, int mask5, int sel) {
    float mx = -1e30f;
    for (int i = 0; i < L; i++) { if (mask5 && i < 5) continue; if (l[i] > mx) mx = l[i]; }
    float s = 0.f;
    for (int i = 0; i < L; i++) { if (mask5 && i < 5) continue; s += expf(l[i] - mx); }
    return expf(l[sel] - mx) / s;
}

__device__ void set_gd(int slot, const float* A, const float* W, const float* bias,
                       int pre, const float* lng, const float* lnb,
                       int epi, const float* mult, const float* residual,
                       float scale, float* C, int accum) {
    GemmDesc& g = g_gd[slot];
    g.active = 1; g.A = A; g.W = W; g.bias = bias;
    g.pre_mode = pre; g.lng = lng; g.lnb = lnb;
    g.epi_act = epi; g.mult = mult; g.residual = residual;
    g.scale = scale; g.C = C; g.accumulate = accum;
}

// Fill an edge slot; returns consumed input node index inn (-2..7)
__device__ int fill_edge(int node, int which, int sel, float w, int lind, int snode,
                         const float* const* bufs,
                         const float* eW, const float* eb, const float* eg, const float* ebe,
                         float* dst) {
    int se = sel / 5, op = sel % 5;
    int inn = (se == 0) ? -2 : (snode + se);
    int e = lind + se;
    const float* src = bufs[inn + 2];
    if (op == 4) {
        CopyDesc& cd = g_cd[node * 3 + which];
        cd.active = 1; cd.src = src; cd.dst = dst; cd.scale = w;
    } else {
        set_gd(node * 7 + which,
               src, eW + (size_t)e * D * D, eb + e * D,
               (op <= 2) ? 1 : 0, eg + e * D, ebe + e * D,
               (op == 0) ? 1 : ((op == 1) ? 2 : 0),
               nullptr, nullptr, w, dst, 0);
    }
    return inn;
}

// ---------------- routing kernel: computes routes + writes all descriptors ----------
__global__ void routing_kernel(const float* inpute, const float* inputo,
                               const float* node_p, const float* edge_p,
                               const float* edge_W, const float* edge_b,
                               const float* edge_g, const float* edge_beta,
                               const float* node_W, const float* node_b,
                               const float* node_g, const float* node_beta) {
    if (threadIdx.x != 0 || blockIdx.x != 0) return;

    const float* bufs[10];
    bufs[0] = inpute; bufs[1] = inputo;
    for (int i = 0; i < 8; i++) bufs[2 + i] = g_outs[i];

    for (int i = 0; i < 56; i++) g_gd[i].active = 0;
    for (int i = 0; i < 24; i++) g_cd[i].active = 0;
    for (int i = 0; i < 8; i++) { g_ed[i].active = 0; g_attn_on[i] = 0; }

    int processed = 0;
    int lind = 0;
    for (int c = 0; c < 8; c++) {
        int nsrc = (c + 2 < 5) ? (c + 2) : 5;
        int snode = c - nsrc;
        int L = nsrc * 5;
        float ep0[25], ep1[25], ep2[25];
        for (int s = 0; s < nsrc; s++)
            for (int j = 0; j < 5; j++) {
                int e = lind + s;
                ep0[s * 5 + j] = edge_p[(0 * NEDGEn + e) * 5 + j];
                ep1[s * 5 + j] = edge_p[(1 * NEDGEn + e) * 5 + j];
                ep2[s * 5 + j] = edge_p[(2 * NEDGEn + e) * 5 + j];
            }
        // node activation argmax + softmax weight
        int nact = 0; float bb = node_p[c * 8];
        for (int i = 1; i < 8; i++) { float x = node_p[c * 8 + i]; if (x > bb) { bb = x; nact = i; } }
        float aw;
        { float sum = 0.f; for (int i = 0; i < 8; i++) sum += expf(node_p[c * 8 + i] - bb);
          aw = expf(node_p[c * 8 + nact] - bb) / sum; }

        // q selection: first 5 masked
        int qsel = 5; float qb = ep0[5];
        for (int i = 6; i < L; i++) if (ep0[i] > qb) { qb = ep0[i]; qsel = i; }
        float wq = selw_masked(ep0, L, 1, qsel);

        int ksel = -1, vsel = -1;
        float wk = 0.f, wv = 0.f;
        int ktype = 0;
        if (nact < 7) {
            int km = (nact > 0) ? 1 : 0;
            int start = km ? 5 : 0;
            ksel = start; float kb = ep1[start];
            for (int i = start + 1; i < L; i++) if (ep1[i] > kb) { kb = ep1[i]; ksel = i; }
            wk = selw_masked(ep1, L, km, ksel);
            ktype = (ksel / 5 == 0) ? -2 : -1;
            if (nact < 5) {
                if (nact == 0 && ktype == -2) {
                    vsel = 0; float vb = ep2[0];
                    for (int i = 1; i < 5; i++) if (ep2[i] > vb) { vb = ep2[i]; vsel = i; }
                    wv = selw_masked(ep2, 5, 0, vsel);
                } else {
                    int vm = km;
                    int vstart = vm ? 5 : 0;
                    vsel = vstart; float vb = ep2[vstart];
                    for (int i = vstart + 1; i < L; i++) if (ep2[i] > vb) { vb = ep2[i]; vsel = i; }
                    wv = selw_masked(ep2, L, vm, vsel);
                }
            }
        }

        // edge descriptors
        float* outc = g_outs[c];
        int inn;
        inn = fill_edge(c, 0, qsel, wq, lind, snode, bufs, edge_W, edge_b, edge_g, edge_beta, g_q);
        processed |= 1 << (inn + 2);
        if (nact < 7) {
            inn = fill_edge(c, 1, ksel, wk, lind, snode, bufs, edge_W, edge_b, edge_g, edge_beta, g_k);
            processed |= 1 << (inn + 2);
        }
        if (nact < 5) {
            inn = fill_edge(c, 2, vsel, wv, lind, snode, bufs, edge_W, edge_b, edge_g, edge_beta, g_v);
            processed |= 1 << (inn + 2);
        }

        // node descriptors
        const float* nw  = node_W + (size_t)c * 4 * D * D;
        const float* nbv = node_b + (size_t)c * 4 * D;
        const float* ngv = node_g + (size_t)c * D;
        const float* nbe = node_beta + (size_t)c * D;
        int s3 = c * 7 + 3, s4 = c * 7 + 4, s5 = c * 7 + 5, s6 = c * 7 + 6;

        if (nact == 0) {
            set_gd(s3, g_q, nw,             nbv,         1, ngv, nbe, 0, nullptr, nullptr, 1.f, g_t1, 0);
            set_gd(s4, g_k, nw + D * D,     nbv + D,     0, nullptr, nullptr, 0, nullptr, nullptr, 1.f, g_t2, 0);
            set_gd(s5, g_v, nw + 2 * D * D, nbv + 2 * D, 0, nullptr, nullptr, 0, nullptr, nullptr, 1.f, g_t3, 0);
            g_attn_on[c] = 1;
            set_gd(s6, g_t4, nw + 3 * D * D, nbv + 3 * D, 0, nullptr, nullptr, 0, nullptr, g_q, aw, outc, 0);
        } else if (nact == 1) {
            set_gd(s3, g_q, nw,         nbv,     0, nullptr, nullptr, 2, nullptr, nullptr, 1.f, g_t1, 0);
            set_gd(s4, g_k, nw + D * D, nbv + D, 0, nullptr, nullptr, 0, g_t1, nullptr, 1.f, g_t4, 0);
            set_gd(s6, g_t4, nw + 3 * D * D, nbv + 3 * D, 0, nullptr, nullptr, 0, nullptr, g_q, aw, outc, 0);
        } else if (nact == 3) {
            set_gd(s3, g_q, nw,             nullptr, 0, nullptr, nullptr, 0, nullptr, nullptr, 1.f, g_t1, 0);
            set_gd(s4, g_k, nw + D * D,     nullptr, 0, nullptr, nullptr, 0, nullptr, nullptr, 1.f, g_t1, 1);
            set_gd(s5, g_v, nw + 2 * D * D, nullptr, 0, nullptr, nullptr, 0, nullptr, nullptr, 1.f, g_t1, 1);
            set_gd(s6, g_t1, nw + 3 * D * D, nbv + 3 * D, 2, nullptr, nullptr, 0, nullptr, g_q, aw, outc, 0);
        } else if (nact == 5) {
            set_gd(s4, g_k, nw + D * D, nbv + D, 0, nullptr, nullptr, 2, nullptr, g_q, aw, outc, 0);
        } else { // 2, 4, 6, 7 elementwise
            ElemDesc& e = g_ed[c];
            e.active = 1; e.opcode = nact;
            e.q = g_q; e.k = g_k; e.v = g_v;
            e.g = ngv; e.b = nbe; e.scale = aw; e.dst = outc;
        }
        lind += nsrc;
    }
    int rem = 0;
    for (int n = 0; n < 8; n++)
        if (!((processed >> (n + 2)) & 1)) rem |= 1 << n;
    g_rem_mask = rem;
}

// ---------------- conv_slot: pre-split A (with pre-op fused) and W for one slot ----
// blocks 0..127: W transpose+split tiles (16 n-tiles x 8 k-tiles)
// blocks 128..639: A rows, 8 rows per block (one warp per row)
__global__ __launch_bounds__(256) void conv_slot(int slot) {
    GemmDesc d = g_gd[slot];
    if (!d.active) return;
    int b = blockIdx.x, tid = threadIdx.x;

    if (b < 128) {
        __shared__ float st[64][33];
        int n0 = (b & 15) * 32, k0 = (b >> 4) * 64;
        int kr = tid >> 2, nq = (tid & 3) * 8;
        const float* src = d.W + (size_t)(k0 + kr) * D + n0 + nq;
        float4 v0 = *(const float4*)src;
        float4 v1 = *(const float4*)(src + 4);
        st[kr][nq + 0] = v0.x; st[kr][nq + 1] = v0.y;
        st[kr][nq + 2] = v0.z; st[kr][nq + 3] = v0.w;
        st[kr][nq + 4] = v1.x; st[kr][nq + 5] = v1.y;
        st[kr][nq + 6] = v1.z; st[kr][nq + 7] = v1.w;
        __syncthreads();
        int n = tid >> 3, k2b = (tid & 7) * 4;
        uint2 o[4];
        #pragma unroll
        for (int i = 0; i < 4; i++) {
            int k2 = k2b + i;
            o[i] = split_pair(st[2 * k2][n], st[2 * k2 + 1][n]);
        }
        uint2* dst = g_Wc + (size_t)slot * 512 * 256 + (size_t)(n0 + n) * 256 + (k0 >> 1) + k2b;
        *(uint4*)dst       = make_uint4(o[0].x, o[0].y, o[1].x, o[1].y);
        *(uint4*)(dst + 2) = make_uint4(o[2].x, o[2].y, o[3].x, o[3].y);
    } else {
        int r = (b - 128) * 8 + (tid >> 5);
        int lane = tid & 31;
        const float* src = d.A + (size_t)r * D + lane * 16;
        float x[16];
        #pragma unroll
        for (int i = 0; i < 4; i++) {
            float4 v = *(const float4*)(src + i * 4);
            x[i * 4 + 0] = v.x; x[i * 4 + 1] = v.y;
            x[i * 4 + 2] = v.z; x[i * 4 + 3] = v.w;
        }
        if (d.pre_mode == 1) {
            float s = 0.f, q = 0.f;
            #pragma unroll
            for (int i = 0; i < 16; i++) { s += x[i]; q += x[i] * x[i]; }
            #pragma unroll
            for (int off = 16; off > 0; off >>= 1) {
                s += __shfl_xor_sync(0xFFFFFFFFu, s, off);
                q += __shfl_xor_sync(0xFFFFFFFFu, q, off);
            }
            float mean = s * (1.f / 512.f);
            float var = q * (1.f / 512.f) - mean * mean;
            float rstd = rsqrtf(var + EPSf);
            #pragma unroll
            for (int i = 0; i < 16; i++) {
                int j = lane * 16 + i;
                x[i] = (x[i] - mean) * rstd * d.lng[j] + d.lnb[j];
            }
        } else if (d.pre_mode == 2) {
            #pragma unroll
            for (int i = 0; i < 16; i++) x[i] = fmaxf(x[i], 0.f);
        }
        uint2 o[8];
        #pragma unroll
        for (int i = 0; i < 8; i++) o[i] = split_pair(x[2 * i], x[2 * i + 1]);
        uint4* dst = (uint4*)(g_Ac + (size_t)r * 256 + lane * 8);
        #pragma unroll
        for (int i = 0; i < 4; i++)
            dst[i] = make_uint4(o[2 * i].x, o[2 * i].y, o[2 * i + 1].x, o[2 * i + 1].y);
    }
}

// ---------------- GEMM slot kernel: bf16 split-2, 3-product mma.m16n8k16 ----------
// C[NTOK,D] = epi( pre(A)[NTOK,D] @ W[D,D] + bias ) (*mult)(+residual)(*scale)
// BM=128, BN=64, BK=32; 8 warps 4(M)x2(N); warp tile 32x32 = 2 m16 x 4 n8.
__global__ __launch_bounds__(256) void gemm_slot(int slot) {
    GemmDesc d = g_gd[slot];
    if (!d.active) return;

    const uint2* __restrict__ Ac = g_Ac;
    const uint2* __restrict__ Wc = g_Wc + (size_t)slot * 512 * 256;

    __shared__ uint2 sA[2][BK2][BM];   // [k2][m] {hi2,lo2}
    __shared__ uint2 sB[2][BK2][BN];   // [k2][n]

    int tid = threadIdx.x;
    int m0 = blockIdx.y * BM;
    int n0 = blockIdx.x * BN;
    int warp = tid >> 5, lane = tid & 31;
    int g = lane >> 2, t = lane & 3;
    int wM = (warp >> 1) * 32;
    int wN = (warp & 1) * 32;

    int arow = tid >> 1, ak2 = (tid & 1) * 8;
    int bn = tid >> 2, bk2 = (tid & 3) * 4;

    float acc[2][4][4];
    #pragma unroll
    for (int a = 0; a < 2; a++)
        #pragma unroll
        for (int bq = 0; bq < 4; bq++)
            #pragma unroll
            for (int cc = 0; cc < 4; cc++) acc[a][bq][cc] = 0.f;

    uint4 ra[4], rb[2];
    {
        const uint4* Ag = (const uint4*)(Ac + (size_t)(m0 + arow) * 256 + ak2);
        const uint4* Bg = (const uint4*)(Wc + (size_t)(n0 + bn) * 256 + bk2);
        #pragma unroll
        for (int i = 0; i < 4; i++) ra[i] = Ag[i];
        rb[0] = Bg[0]; rb[1] = Bg[1];
    }

    for (int kt = 0; kt < D / BK; kt++) {
        int buf = kt & 1;
        #pragma unroll
        for (int i = 0; i < 4; i++) {
            sA[buf][ak2 + 2 * i][arow]     = make_uint2(ra[i].x, ra[i].y);
            sA[buf][ak2 + 2 * i + 1][arow] = make_uint2(ra[i].z, ra[i].w);
        }
        #pragma unroll
        for (int i = 0; i < 2; i++) {
            sB[buf][bk2 + 2 * i][bn]     = make_uint2(rb[i].x, rb[i].y);
            sB[buf][bk2 + 2 * i + 1][bn] = make_uint2(rb[i].z, rb[i].w);
        }
        __syncthreads();
        if (kt + 1 < D / BK) {
            int kb = (kt + 1) * BK2;
            const uint4* Ag = (const uint4*)(Ac + (size_t)(m0 + arow) * 256 + kb + ak2);
            const uint4* Bg = (const uint4*)(Wc + (size_t)(n0 + bn) * 256 + kb + bk2);
            #pragma unroll
            for (int i = 0; i < 4; i++) ra[i] = Ag[i];
            rb[0] = Bg[0]; rb[1] = Bg[1];
        }
        #pragma unroll
        for (int c = 0; c < 2; c++) {
            int k2a = c * 8 + t, k2b2 = c * 8 + t + 4;
            uint32_t ahi[2][4], alo[2][4];
            #pragma unroll
            for (int mt = 0; mt < 2; mt++) {
                uint2 v0 = sA[buf][k2a][wM + mt * 16 + g];
                uint2 v1 = sA[buf][k2a][wM + mt * 16 + g + 8];
                uint2 v2 = sA[buf][k2b2][wM + mt * 16 + g];
                uint2 v3 = sA[buf][k2b2][wM + mt * 16 + g + 8];
                ahi[mt][0] = v0.x; ahi[mt][1] = v1.x; ahi[mt][2] = v2.x; ahi[mt][3] = v3.x;
                alo[mt][0] = v0.y; alo[mt][1] = v1.y; alo[mt][2] = v2.y; alo[mt][3] = v3.y;
            }
            uint32_t bhi[4][2], blo[4][2];
            #pragma unroll
            for (int nt = 0; nt < 4; nt++) {
                uint2 w0 = sB[buf][k2a][wN + nt * 8 + g];
                uint2 w1 = sB[buf][k2b2][wN + nt * 8 + g];
                bhi[nt][0] = w0.x; bhi[nt][1] = w1.x;
                blo[nt][0] = w0.y; blo[nt][1] = w1.y;
            }
            #pragma unroll
            for (int mt = 0; mt < 2; mt++)
                #pragma unroll
                for (int nt = 0; nt < 4; nt++) {
                    mma_bf16(acc[mt][nt], ahi[mt], bhi[nt]);
                    mma_bf16(acc[mt][nt], ahi[mt], blo[nt]);
                    mma_bf16(acc[mt][nt], alo[mt], bhi[nt]);
                }
        }
        __syncthreads();
    }

    // epilogue
    #pragma unroll
    for (int mt = 0; mt < 2; mt++)
        #pragma unroll
        for (int nt = 0; nt < 4; nt++) {
            int m = m0 + wM + mt * 16 + g;
            int n = n0 + wN + nt * 8 + 2 * t;
            float b0v = 0.f, b1v = 0.f;
            if (d.bias) { b0v = d.bias[n]; b1v = d.bias[n + 1]; }
            #pragma unroll
            for (int rr = 0; rr < 2; rr++) {
                int mr = m + rr * 8;
                float x0 = acc[mt][nt][rr * 2 + 0] + b0v;
                float x1 = acc[mt][nt][rr * 2 + 1] + b1v;
                if (d.epi_act == 1) { x0 = fmaxf(x0, 0.f); x1 = fmaxf(x1, 0.f); }
                else if (d.epi_act == 2) { x0 = gelu_f(x0); x1 = gelu_f(x1); }
                if (d.mult) {
                    float2 mv = *(const float2*)(d.mult + (size_t)mr * D + n);
                    x0 *= mv.x; x1 *= mv.y;
                }
                if (d.residual) {
                    float2 rv = *(const float2*)(d.residual + (size_t)mr * D + n);
                    x0 += rv.x; x1 += rv.y;
                }
                x0 *= d.scale; x1 *= d.scale;
                if (d.accumulate) {
                    float2 cv = *(const float2*)(d.C + (size_t)mr * D + n);
                    x0 += cv.x; x1 += cv.y;
                }
                *(float2*)(d.C + (size_t)mr * D + n) = make_float2(x0, x1);
            }
        }
}

// ---------------- edge op4 copy-scale ----------------
__global__ void copy_slot(int slot) {
    CopyDesc d = g_cd[slot];
    if (!d.active) return;
    int i = blockIdx.x * blockDim.x + threadIdx.x;
    int stride = gridDim.x * blockDim.x;
    const float4* src = (const float4*)d.src;
    float4* dst = (float4*)d.dst;
    for (; i < NTOK * D / 4; i += stride) {
        float4 v = src[i];
        v.x *= d.scale; v.y *= d.scale; v.z *= d.scale; v.w *= d.scale;
        dst[i] = v;
    }
}

// ---------------- attention (act 0): one warp per query row, online softmax ------
__global__ __launch_bounds__(256) void attn_slot(int c) {
    if (!g_attn_on[c]) return;
    int warp = threadIdx.x >> 5, lane = threadIdx.x & 31;
    int bh = blockIdx.x;            // 0..31
    int b = bh >> 3, h = bh & 7;
    int s = blockIdx.y * 8 + warp;  // 0..1023

    const float* qrow = g_t1 + (size_t)((b << 10) + s) * D + h * 64 + lane * 2;
    float q0 = qrow[0], q1 = qrow[1];
    const float* kbase = g_t2 + (size_t)(b << 10) * D + h * 64 + lane * 2;
    const float* vbase = g_t3 + (size_t)(b << 10) * D + h * 64 + lane * 2;

    float m = -1e30f, l = 0.f, a0 = 0.f, a1 = 0.f;
    for (int sk = 0; sk < 1024; sk++) {
        float2 kk = *(const float2*)(kbase + (size_t)sk * D);
        float p = q0 * kk.x + q1 * kk.y;
        p += __shfl_xor_sync(0xFFFFFFFFu, p, 16);
        p += __shfl_xor_sync(0xFFFFFFFFu, p, 8);
        p += __shfl_xor_sync(0xFFFFFFFFu, p, 4);
        p += __shfl_xor_sync(0xFFFFFFFFu, p, 2);
        p += __shfl_xor_sync(0xFFFFFFFFu, p, 1);
        float dot = p * 0.125f;
        float mn = fmaxf(m, dot);
        float corr = __expf(m - mn);
        float w = __expf(dot - mn);
        float2 vv = *(const float2*)(vbase + (size_t)sk * D);
        l = l * corr + w;
        a0 = a0 * corr + w * vv.x;
        a1 = a1 * corr + w * vv.y;
        m = mn;
    }
    float inv = 1.f / l;
    float* orow = g_t4 + (size_t)((b << 10) + s) * D + h * 64 + lane * 2;
    orow[0] = a0 * inv;
    orow[1] = a1 * inv;
}

// ---------------- elementwise node ops (acts 2,4,6,7) ----------------
__global__ __launch_bounds__(256) void elem_node_kernel(int c) {
    ElemDesc d = g_ed[c];
    if (!d.active) return;
    int row = blockIdx.x;
    int tid = threadIdx.x;
    size_t base = (size_t)row * D;
    float x[2];
    #pragma unroll
    for (int i = 0; i < 2; i++) {
        int j = tid + i * 256;
        float qv = d.q[base + j];
        if (d.opcode == 2) x[i] = qv + d.k[base + j] + d.v[base + j];
        else if (d.opcode == 4) {
            float kv = d.k[base + j];
            x[i] = qv * (1.f / (1.f + expf(-kv))) + d.v[base + j];
        }
        else if (d.opcode == 6) x[i] = qv + d.k[base + j];
        else x[i] = qv; // 7
    }
    if (d.opcode == 2 || d.opcode == 7) {
        __shared__ float rs[256], rq[256];
        rs[tid] = x[0] + x[1];
        rq[tid] = x[0] * x[0] + x[1] * x[1];
        __syncthreads();
        for (int off = 128; off > 0; off >>= 1) {
            if (tid < off) { rs[tid] += rs[tid + off]; rq[tid] += rq[tid + off]; }
            __syncthreads();
        }
        float mean = rs[0] * (1.f / 512.f);
        float var = rq[0] * (1.f / 512.f) - mean * mean;
        float rstd = rsqrtf(var + EPSf);
        #pragma unroll
        for (int i = 0; i < 2; i++) {
            int j = tid + i * 256;
            d.dst[base + j] = d.scale * ((x[i] - mean) * rstd * d.g[j] + d.b[j]);
        }
    } else {
        #pragma unroll
        for (int i = 0; i < 2; i++) {
            int j = tid + i * 256;
            d.dst[base + j] = d.scale * x[i];
        }
    }
}

// ---------------- final: sum remaining outs + LayerNorm ----------------
__global__ __launch_bounds__(256) void final_kernel(const float* out_g, const float* out_beta,
                                                    float* out) {
    int row = blockIdx.x;
    int tid = threadIdx.x;
    int mask = g_rem_mask;
    size_t base = (size_t)row * D;
    float x[2];
    #pragma unroll
    for (int i = 0; i < 2; i++) {
        int j = tid + i * 256;
        float s = 0.f;
        for (int n = 0; n < 8; n++)
            if ((mask >> n) & 1) s += g_outs[n][base + j];
        x[i] = s;
    }
    __shared__ float rs[256], rq[256];
    rs[tid] = x[0] + x[1];
    rq[tid] = x[0] * x[0] + x[1] * x[1];
    __syncthreads();
    for (int off = 128; off > 0; off >>= 1) {
        if (tid < off) { rs[tid] += rs[tid + off]; rq[tid] += rq[tid + off]; }
        __syncthreads();
    }
    float mean = rs[0] * (1.f / 512.f);
    float var = rq[0] * (1.f / 512.f) - mean * mean;
    float rstd = rsqrtf(var + EPSf);
    #pragma unroll
    for (int i = 0; i < 2; i++) {
        int j = tid + i * 256;
        out[base + j] = (x[i] - mean) * rstd * out_g[j] + out_beta[j];
    }
}

// ---------------- launch ----------------
extern "C" void kernel_launch(void* const* d_in, const int* in_sizes, int n_in,
                              void* d_out, int out_size) {
    const float* inpute   = (const float*)d_in[0];
    const float* inputo   = (const float*)d_in[1];
    const float* node_p   = (const float*)d_in[2];
    const float* edge_p   = (const float*)d_in[3];
    const float* edge_W   = (const float*)d_in[4];
    const float* edge_b   = (const float*)d_in[5];
    const float* edge_g   = (const float*)d_in[6];
    const float* edge_bet = (const float*)d_in[7];
    const float* node_W   = (const float*)d_in[8];
    const float* node_b   = (const float*)d_in[9];
    const float* node_g   = (const float*)d_in[10];
    const float* node_bet = (const float*)d_in[11];
    const float* out_g    = (const float*)d_in[12];
    const float* out_bet  = (const float*)d_in[13];
    float* out = (float*)d_out;

    routing_kernel<<<1, 1>>>(inpute, inputo, node_p, edge_p,
                             edge_W, edge_b, edge_g, edge_bet,
                             node_W, node_b, node_g, node_bet);

    dim3 ggrid(D / BN, NTOK / BM);   // (8, 32)
    for (int c = 0; c < 8; c++) {
        for (int w = 0; w < 3; w++) {
            conv_slot<<<640, 256>>>(c * 7 + w);
            gemm_slot<<<ggrid, 256>>>(c * 7 + w);
            copy_slot<<<512, 256>>>(c * 3 + w);
        }
        for (int w = 3; w < 6; w++) {
            conv_slot<<<640, 256>>>(c * 7 + w);
            gemm_slot<<<ggrid, 256>>>(c * 7 + w);
        }
        attn_slot<<<dim3(32, 128), 256>>>(c);
        conv_slot<<<640, 256>>>(c * 7 + 6);
        gemm_slot<<<ggrid, 256>>>(c * 7 + 6);
        elem_node_kernel<<<NTOK, 256>>>(c);
    }
    final_kernel<<<NTOK, 256>>>(out_g, out_bet, out);
}

// round 6
// speedup vs baseline: 1.2317x; 1.2317x over previous
#include <cuda_runtime.h>
#include <cuda_bf16.h>
#include <math.h>
#include <stdint.h>

#define D       512
#define NTOK    4096      // B*SLEN = 4*1024
#define NNODn   8
#define NEDGEn  34
#define EPSf    1e-6f

// GEMM tile
#define BM 128
#define BN 64
#define BK 32        // k per stage
#define BK2 16       // k2 pairs per stage

// ---------------- scratch buffers (device globals; no allocation allowed) ----------
__device__ float g_outs[8][NTOK * D];
__device__ float g_q[NTOK * D];
__device__ float g_k[NTOK * D];
__device__ float g_v[NTOK * D];
__device__ float g_t1[NTOK * D];
__device__ float g_t2[NTOK * D];
__device__ float g_t3[NTOK * D];
__device__ float g_t4[NTOK * D];

// ---------------- descriptors ----------------
struct GemmDesc {
    int active;
    int pre_mode;    // 0 none, 1 LN(A), 2 relu(A)
    int epi_act;     // 0 none, 1 relu, 2 gelu
    int accumulate;  // 1: C += result
    const float *A, *W, *bias, *lng, *lnb, *mult, *residual;
    float scale;
    float *C;
};
struct CopyDesc { int active; const float* src; float* dst; float scale; };
struct ElemDesc {
    int active; int opcode;   // 2,4,6,7
    const float *q, *k, *v, *g, *b;
    float scale; float* dst;
};

__device__ GemmDesc g_gd[56];   // node*7 + {EQ,EK,EV,G1,G2,G3,G4}
__device__ CopyDesc g_cd[24];   // node*3 + {q,k,v}
__device__ ElemDesc g_ed[8];
__device__ int g_attn_on[8];
__device__ int g_rem_mask;

// ---------------- bf16 split helpers ----------------
// pack (x0 = even k, x1 = odd k): .x = hi bf16x2, .y = lo bf16x2
__device__ __forceinline__ uint2 split_pair(float x0, float x1) {
    __nv_bfloat162 hh;
    asm("cvt.rn.bf16x2.f32 %0, %1, %2;" : "=r"(*(uint32_t*)&hh) : "f"(x1), "f"(x0));
    float l0 = x0 - __bfloat162float(hh.x);
    float l1 = x1 - __bfloat162float(hh.y);
    uint32_t ll;
    asm("cvt.rn.bf16x2.f32 %0, %1, %2;" : "=r"(ll) : "f"(l1), "f"(l0));
    uint2 r;
    r.x = *(uint32_t*)&hh;
    r.y = ll;
    return r;
}

__device__ __forceinline__ void mma_bf16(float* c, const uint32_t* a, const uint32_t* b) {
    asm volatile(
        "mma.sync.aligned.m16n8k16.row.col.f32.bf16.bf16.f32 "
        "{%0,%1,%2,%3}, {%4,%5,%6,%7}, {%8,%9}, {%0,%1,%2,%3};"
        : "+f"(c[0]), "+f"(c[1]), "+f"(c[2]), "+f"(c[3])
        : "r"(a[0]), "r"(a[1]), "r"(a[2]), "r"(a[3]),
          "r"(b[0]), "r"(b[1]));
}

// ---------------- small helpers ----------------
__device__ __forceinline__ float gelu_f(float x) {
    const float k0 = 0.7978845608028654f;
    float x3 = x * x * x;
    return 0.5f * x * (1.f + tanhf(k0 * (x + 0.044715f * x3)));
}

__device__ float selw_masked(const float* l, int L, int mask5, int sel) {
    float mx = -1e30f;
    for (int i = 0; i < L; i++) { if (mask5 && i < 5) continue; if (l[i] > mx) mx = l[i]; }
    float s = 0.f;
    for (int i = 0; i < L; i++) { if (mask5 && i < 5) continue; s += expf(l[i] - mx); }
    return expf(l[sel] - mx) / s;
}

__device__ void set_gd(int slot, const float* A, const float* W, const float* bias,
                       int pre, const float* lng, const float* lnb,
                       int epi, const float* mult, const float* residual,
                       float scale, float* C, int accum) {
    GemmDesc& g = g_gd[slot];
    g.active = 1; g.A = A; g.W = W; g.bias = bias;
    g.pre_mode = pre; g.lng = lng; g.lnb = lnb;
    g.epi_act = epi; g.mult = mult; g.residual = residual;
    g.scale = scale; g.C = C; g.accumulate = accum;
}

// Fill an edge slot; returns consumed input node index inn (-2..7)
__device__ int fill_edge(int node, int which, int sel, float w, int lind, int snode,
                         const float* const* bufs,
                         const float* eW, const float* eb, const float* eg, const float* ebe,
                         float* dst) {
    int se = sel / 5, op = sel % 5;
    int inn = (se == 0) ? -2 : (snode + se);
    int e = lind + se;
    const float* src = bufs[inn + 2];
    if (op == 4) {
        CopyDesc& cd = g_cd[node * 3 + which];
        cd.active = 1; cd.src = src; cd.dst = dst; cd.scale = w;
    } else {
        set_gd(node * 7 + which,
               src, eW + (size_t)e * D * D, eb + e * D,
               (op <= 2) ? 1 : 0, eg + e * D, ebe + e * D,
               (op == 0) ? 1 : ((op == 1) ? 2 : 0),
               nullptr, nullptr, w, dst, 0);
    }
    return inn;
}

// ---------------- routing kernel: computes routes + writes all descriptors ----------
__global__ void routing_kernel(const float* inpute, const float* inputo,
                               const float* node_p, const float* edge_p,
                               const float* edge_W, const float* edge_b,
                               const float* edge_g, const float* edge_beta,
                               const float* node_W, const float* node_b,
                               const float* node_g, const float* node_beta) {
    if (threadIdx.x != 0 || blockIdx.x != 0) return;

    const float* bufs[10];
    bufs[0] = inpute; bufs[1] = inputo;
    for (int i = 0; i < 8; i++) bufs[2 + i] = g_outs[i];

    for (int i = 0; i < 56; i++) g_gd[i].active = 0;
    for (int i = 0; i < 24; i++) g_cd[i].active = 0;
    for (int i = 0; i < 8; i++) { g_ed[i].active = 0; g_attn_on[i] = 0; }

    int processed = 0;
    int lind = 0;
    for (int c = 0; c < 8; c++) {
        int nsrc = (c + 2 < 5) ? (c + 2) : 5;
        int snode = c - nsrc;
        int L = nsrc * 5;
        float ep0[25], ep1[25], ep2[25];
        for (int s = 0; s < nsrc; s++)
            for (int j = 0; j < 5; j++) {
                int e = lind + s;
                ep0[s * 5 + j] = edge_p[(0 * NEDGEn + e) * 5 + j];
                ep1[s * 5 + j] = edge_p[(1 * NEDGEn + e) * 5 + j];
                ep2[s * 5 + j] = edge_p[(2 * NEDGEn + e) * 5 + j];
            }
        // node activation argmax + softmax weight
        int nact = 0; float bb = node_p[c * 8];
        for (int i = 1; i < 8; i++) { float x = node_p[c * 8 + i]; if (x > bb) { bb = x; nact = i; } }
        float aw;
        { float sum = 0.f; for (int i = 0; i < 8; i++) sum += expf(node_p[c * 8 + i] - bb);
          aw = expf(node_p[c * 8 + nact] - bb) / sum; }

        // q selection: first 5 masked
        int qsel = 5; float qb = ep0[5];
        for (int i = 6; i < L; i++) if (ep0[i] > qb) { qb = ep0[i]; qsel = i; }
        float wq = selw_masked(ep0, L, 1, qsel);

        int ksel = -1, vsel = -1;
        float wk = 0.f, wv = 0.f;
        int ktype = 0;
        if (nact < 7) {
            int km = (nact > 0) ? 1 : 0;
            int start = km ? 5 : 0;
            ksel = start; float kb = ep1[start];
            for (int i = start + 1; i < L; i++) if (ep1[i] > kb) { kb = ep1[i]; ksel = i; }
            wk = selw_masked(ep1, L, km, ksel);
            ktype = (ksel / 5 == 0) ? -2 : -1;
            if (nact < 5) {
                if (nact == 0 && ktype == -2) {
                    vsel = 0; float vb = ep2[0];
                    for (int i = 1; i < 5; i++) if (ep2[i] > vb) { vb = ep2[i]; vsel = i; }
                    wv = selw_masked(ep2, 5, 0, vsel);
                } else {
                    int vm = km;
                    int vstart = vm ? 5 : 0;
                    vsel = vstart; float vb = ep2[vstart];
                    for (int i = vstart + 1; i < L; i++) if (ep2[i] > vb) { vb = ep2[i]; vsel = i; }
                    wv = selw_masked(ep2, L, vm, vsel);
                }
            }
        }

        // edge descriptors
        float* outc = g_outs[c];
        int inn;
        inn = fill_edge(c, 0, qsel, wq, lind, snode, bufs, edge_W, edge_b, edge_g, edge_beta, g_q);
        processed |= 1 << (inn + 2);
        if (nact < 7) {
            inn = fill_edge(c, 1, ksel, wk, lind, snode, bufs, edge_W, edge_b, edge_g, edge_beta, g_k);
            processed |= 1 << (inn + 2);
        }
        if (nact < 5) {
            inn = fill_edge(c, 2, vsel, wv, lind, snode, bufs, edge_W, edge_b, edge_g, edge_beta, g_v);
            processed |= 1 << (inn + 2);
        }

        // node descriptors
        const float* nw  = node_W + (size_t)c * 4 * D * D;
        const float* nbv = node_b + (size_t)c * 4 * D;
        const float* ngv = node_g + (size_t)c * D;
        const float* nbe = node_beta + (size_t)c * D;
        int s3 = c * 7 + 3, s4 = c * 7 + 4, s5 = c * 7 + 5, s6 = c * 7 + 6;

        if (nact == 0) {
            set_gd(s3, g_q, nw,             nbv,         1, ngv, nbe, 0, nullptr, nullptr, 1.f, g_t1, 0);
            set_gd(s4, g_k, nw + D * D,     nbv + D,     0, nullptr, nullptr, 0, nullptr, nullptr, 1.f, g_t2, 0);
            set_gd(s5, g_v, nw + 2 * D * D, nbv + 2 * D, 0, nullptr, nullptr, 0, nullptr, nullptr, 1.f, g_t3, 0);
            g_attn_on[c] = 1;
            set_gd(s6, g_t4, nw + 3 * D * D, nbv + 3 * D, 0, nullptr, nullptr, 0, nullptr, g_q, aw, outc, 0);
        } else if (nact == 1) {
            set_gd(s3, g_q, nw,         nbv,     0, nullptr, nullptr, 2, nullptr, nullptr, 1.f, g_t1, 0);
            set_gd(s4, g_k, nw + D * D, nbv + D, 0, nullptr, nullptr, 0, g_t1, nullptr, 1.f, g_t4, 0);
            set_gd(s6, g_t4, nw + 3 * D * D, nbv + 3 * D, 0, nullptr, nullptr, 0, nullptr, g_q, aw, outc, 0);
        } else if (nact == 3) {
            set_gd(s3, g_q, nw,             nullptr, 0, nullptr, nullptr, 0, nullptr, nullptr, 1.f, g_t1, 0);
            set_gd(s4, g_k, nw + D * D,     nullptr, 0, nullptr, nullptr, 0, nullptr, nullptr, 1.f, g_t1, 1);
            set_gd(s5, g_v, nw + 2 * D * D, nullptr, 0, nullptr, nullptr, 0, nullptr, nullptr, 1.f, g_t1, 1);
            set_gd(s6, g_t1, nw + 3 * D * D, nbv + 3 * D, 2, nullptr, nullptr, 0, nullptr, g_q, aw, outc, 0);
        } else if (nact == 5) {
            set_gd(s4, g_k, nw + D * D, nbv + D, 0, nullptr, nullptr, 2, nullptr, g_q, aw, outc, 0);
        } else { // 2, 4, 6, 7 elementwise
            ElemDesc& e = g_ed[c];
            e.active = 1; e.opcode = nact;
            e.q = g_q; e.k = g_k; e.v = g_v;
            e.g = ngv; e.b = nbe; e.scale = aw; e.dst = outc;
        }
        lind += nsrc;
    }
    int rem = 0;
    for (int n = 0; n < 8; n++)
        if (!((processed >> (n + 2)) & 1)) rem |= 1 << n;
    g_rem_mask = rem;
}

// ---------------- GEMM slot kernel: bf16 split-2, 3-product mma.m16n8k16 ----------
// C[NTOK,D] = epi( pre(A)[NTOK,D] @ W[D,D] + bias ) (*mult)(+residual)(*scale)
// BM=128, BN=64, BK=32; 8 warps 4(M)x2(N); warp tile 32x32 = 2 m16 x 4 n8.
__global__ __launch_bounds__(256) void gemm_slot(int slot) {
    GemmDesc d = g_gd[slot];
    if (!d.active) return;

    __shared__ uint2 sA[BK2][BM + 4];   // [k2][m] {hi2,lo2}; stride 132 u2 -> 8-bank k2 offset
    __shared__ uint2 sB[BK2][BN + 4];   // [k2][n]
    __shared__ float s_mean[BM], s_rstd[BM];

    int tid = threadIdx.x;
    int m0 = blockIdx.y * BM;
    int n0 = blockIdx.x * BN;

    if (d.pre_mode == 1) {
        __shared__ float red_s[256], red_q[256];
        int r = tid >> 1, p = tid & 1;
        const float4* row = (const float4*)(d.A + (size_t)(m0 + r) * D + p * 256);
        float s = 0.f, q = 0.f;
        #pragma unroll
        for (int i = 0; i < 64; i++) {
            float4 v = row[i];
            s += v.x + v.y + v.z + v.w;
            q += v.x * v.x + v.y * v.y + v.z * v.z + v.w * v.w;
        }
        red_s[tid] = s; red_q[tid] = q;
        __syncthreads();
        if (p == 0) {
            float S = red_s[tid] + red_s[tid + 1];
            float Q = red_q[tid] + red_q[tid + 1];
            float m = S * (1.f / 512.f);
            float var = Q * (1.f / 512.f) - m * m;
            s_mean[r] = m; s_rstd[r] = rsqrtf(var + EPSf);
        }
        __syncthreads();
    }

    int warp = tid >> 5, lane = tid & 31;
    int g = lane >> 2, t = lane & 3;
    int wM = (warp >> 1) * 32;    // 4 warps along M
    int wN = (warp & 1) * 32;     // 2 warps along N

    // staging mappings
    int arow = tid & 127;          // A row within tile
    int ak0 = (tid >> 7) * 16;     // A k offset within stage: 0 or 16
    int ak20 = (tid >> 7) * 8;     // A k2 offset: 0 or 8
    int wk2 = tid >> 4;            // W k2 row 0..15
    int wn = (tid & 15) * 4;       // W n quad

    float acc[2][4][4];
    #pragma unroll
    for (int a = 0; a < 2; a++)
        #pragma unroll
        for (int bq = 0; bq < 4; bq++)
            #pragma unroll
            for (int cc = 0; cc < 4; cc++) acc[a][bq][cc] = 0.f;

    float4 aval[4];   // A: row arow, 16 consecutive k
    float4 wv0, wv1;  // W: rows 2*wk2, 2*wk2+1, 4 n
    {
        const float* ap = d.A + (size_t)(m0 + arow) * D + ak0;
        #pragma unroll
        for (int i = 0; i < 4; i++) aval[i] = *(const float4*)(ap + i * 4);
        wv0 = *(const float4*)(d.W + (size_t)(2 * wk2) * D + n0 + wn);
        wv1 = *(const float4*)(d.W + (size_t)(2 * wk2 + 1) * D + n0 + wn);
    }

    for (int kt = 0; kt < D / BK; kt++) {
        // transform + split + store to smem
        {
            float x[16];
            #pragma unroll
            for (int i = 0; i < 4; i++) {
                x[i * 4 + 0] = aval[i].x; x[i * 4 + 1] = aval[i].y;
                x[i * 4 + 2] = aval[i].z; x[i * 4 + 3] = aval[i].w;
            }
            if (d.pre_mode == 1) {
                float mn = s_mean[arow], rs = s_rstd[arow];
                int kg = kt * BK + ak0;
                #pragma unroll
                for (int i = 0; i < 16; i++)
                    x[i] = (x[i] - mn) * rs * d.lng[kg + i] + d.lnb[kg + i];
            } else if (d.pre_mode == 2) {
                #pragma unroll
                for (int i = 0; i < 16; i++) x[i] = fmaxf(x[i], 0.f);
            }
            #pragma unroll
            for (int i = 0; i < 8; i++)
                sA[ak20 + i][arow] = split_pair(x[2 * i], x[2 * i + 1]);
            sB[wk2][wn + 0] = split_pair(wv0.x, wv1.x);
            sB[wk2][wn + 1] = split_pair(wv0.y, wv1.y);
            sB[wk2][wn + 2] = split_pair(wv0.z, wv1.z);
            sB[wk2][wn + 3] = split_pair(wv0.w, wv1.w);
        }
        __syncthreads();
        // prefetch next stage into regs
        if (kt + 1 < D / BK) {
            int kb = (kt + 1) * BK;
            const float* ap = d.A + (size_t)(m0 + arow) * D + kb + ak0;
            #pragma unroll
            for (int i = 0; i < 4; i++) aval[i] = *(const float4*)(ap + i * 4);
            wv0 = *(const float4*)(d.W + (size_t)(kb + 2 * wk2) * D + n0 + wn);
            wv1 = *(const float4*)(d.W + (size_t)(kb + 2 * wk2 + 1) * D + n0 + wn);
        }
        // compute: 2 k16 steps
        #pragma unroll
        for (int c = 0; c < 2; c++) {
            int k2a = c * 8 + t, k2b = c * 8 + t + 4;
            uint32_t ahi[2][4], alo[2][4];
            #pragma unroll
            for (int mt = 0; mt < 2; mt++) {
                uint2 v0 = sA[k2a][wM + mt * 16 + g];
                uint2 v1 = sA[k2a][wM + mt * 16 + g + 8];
                uint2 v2 = sA[k2b][wM + mt * 16 + g];
                uint2 v3 = sA[k2b][wM + mt * 16 + g + 8];
                ahi[mt][0] = v0.x; ahi[mt][1] = v1.x; ahi[mt][2] = v2.x; ahi[mt][3] = v3.x;
                alo[mt][0] = v0.y; alo[mt][1] = v1.y; alo[mt][2] = v2.y; alo[mt][3] = v3.y;
            }
            uint32_t bhi[4][2], blo[4][2];
            #pragma unroll
            for (int nt = 0; nt < 4; nt++) {
                uint2 w0 = sB[k2a][wN + nt * 8 + g];
                uint2 w1 = sB[k2b][wN + nt * 8 + g];
                bhi[nt][0] = w0.x; bhi[nt][1] = w1.x;
                blo[nt][0] = w0.y; blo[nt][1] = w1.y;
            }
            #pragma unroll
            for (int mt = 0; mt < 2; mt++)
                #pragma unroll
                for (int nt = 0; nt < 4; nt++) {
                    mma_bf16(acc[mt][nt], ahi[mt], bhi[nt]);
                    mma_bf16(acc[mt][nt], ahi[mt], blo[nt]);
                    mma_bf16(acc[mt][nt], alo[mt], bhi[nt]);
                }
        }
        __syncthreads();
    }

    // epilogue
    #pragma unroll
    for (int mt = 0; mt < 2; mt++)
        #pragma unroll
        for (int nt = 0; nt < 4; nt++) {
            int m = m0 + wM + mt * 16 + g;
            int n = n0 + wN + nt * 8 + 2 * t;
            float b0v = 0.f, b1v = 0.f;
            if (d.bias) { b0v = d.bias[n]; b1v = d.bias[n + 1]; }
            #pragma unroll
            for (int rr = 0; rr < 2; rr++) {
                int mr = m + rr * 8;
                float x0 = acc[mt][nt][rr * 2 + 0] + b0v;
                float x1 = acc[mt][nt][rr * 2 + 1] + b1v;
                if (d.epi_act == 1) { x0 = fmaxf(x0, 0.f); x1 = fmaxf(x1, 0.f); }
                else if (d.epi_act == 2) { x0 = gelu_f(x0); x1 = gelu_f(x1); }
                if (d.mult) {
                    float2 mv = *(const float2*)(d.mult + (size_t)mr * D + n);
                    x0 *= mv.x; x1 *= mv.y;
                }
                if (d.residual) {
                    float2 rv = *(const float2*)(d.residual + (size_t)mr * D + n);
                    x0 += rv.x; x1 += rv.y;
                }
                x0 *= d.scale; x1 *= d.scale;
                if (d.accumulate) {
                    float2 cv = *(const float2*)(d.C + (size_t)mr * D + n);
                    x0 += cv.x; x1 += cv.y;
                }
                *(float2*)(d.C + (size_t)mr * D + n) = make_float2(x0, x1);
            }
        }
}

// ---------------- edge op4 copy-scale ----------------
__global__ void copy_slot(int slot) {
    CopyDesc d = g_cd[slot];
    if (!d.active) return;
    int i = blockIdx.x * blockDim.x + threadIdx.x;
    int stride = gridDim.x * blockDim.x;
    const float4* src = (const float4*)d.src;
    float4* dst = (float4*)d.dst;
    for (; i < NTOK * D / 4; i += stride) {
        float4 v = src[i];
        v.x *= d.scale; v.y *= d.scale; v.z *= d.scale; v.w *= d.scale;
        dst[i] = v;
    }
}

// ---------------- attention (act 0): one warp per query row, online softmax ------
__global__ __launch_bounds__(256) void attn_slot(int c) {
    if (!g_attn_on[c]) return;
    int warp = threadIdx.x >> 5, lane = threadIdx.x & 31;
    int bh = blockIdx.x;            // 0..31
    int b = bh >> 3, h = bh & 7;
    int s = blockIdx.y * 8 + warp;  // 0..1023

    const float* qrow = g_t1 + (size_t)((b << 10) + s) * D + h * 64 + lane * 2;
    float q0 = qrow[0], q1 = qrow[1];
    const float* kbase = g_t2 + (size_t)(b << 10) * D + h * 64 + lane * 2;
    const float* vbase = g_t3 + (size_t)(b << 10) * D + h * 64 + lane * 2;

    float m = -1e30f, l = 0.f, a0 = 0.f, a1 = 0.f;
    for (int sk = 0; sk < 1024; sk++) {
        float2 kk = *(const float2*)(kbase + (size_t)sk * D);
        float p = q0 * kk.x + q1 * kk.y;
        p += __shfl_xor_sync(0xFFFFFFFFu, p, 16);
        p += __shfl_xor_sync(0xFFFFFFFFu, p, 8);
        p += __shfl_xor_sync(0xFFFFFFFFu, p, 4);
        p += __shfl_xor_sync(0xFFFFFFFFu, p, 2);
        p += __shfl_xor_sync(0xFFFFFFFFu, p, 1);
        float dot = p * 0.125f;
        float mn = fmaxf(m, dot);
        float corr = __expf(m - mn);
        float w = __expf(dot - mn);
        float2 vv = *(const float2*)(vbase + (size_t)sk * D);
        l = l * corr + w;
        a0 = a0 * corr + w * vv.x;
        a1 = a1 * corr + w * vv.y;
        m = mn;
    }
    float inv = 1.f / l;
    float* orow = g_t4 + (size_t)((b << 10) + s) * D + h * 64 + lane * 2;
    orow[0] = a0 * inv;
    orow[1] = a1 * inv;
}

// ---------------- elementwise node ops (acts 2,4,6,7) ----------------
__global__ __launch_bounds__(256) void elem_node_kernel(int c) {
    ElemDesc d = g_ed[c];
    if (!d.active) return;
    int row = blockIdx.x;
    int tid = threadIdx.x;
    size_t base = (size_t)row * D;
    float x[2];
    #pragma unroll
    for (int i = 0; i < 2; i++) {
        int j = tid + i * 256;
        float qv = d.q[base + j];
        if (d.opcode == 2) x[i] = qv + d.k[base + j] + d.v[base + j];
        else if (d.opcode == 4) {
            float kv = d.k[base + j];
            x[i] = qv * (1.f / (1.f + expf(-kv))) + d.v[base + j];
        }
        else if (d.opcode == 6) x[i] = qv + d.k[base + j];
        else x[i] = qv; // 7
    }
    if (d.opcode == 2 || d.opcode == 7) {
        __shared__ float rs[256], rq[256];
        rs[tid] = x[0] + x[1];
        rq[tid] = x[0] * x[0] + x[1] * x[1];
        __syncthreads();
        for (int off = 128; off > 0; off >>= 1) {
            if (tid < off) { rs[tid] += rs[tid + off]; rq[tid] += rq[tid + off]; }
            __syncthreads();
        }
        float mean = rs[0] * (1.f / 512.f);
        float var = rq[0] * (1.f / 512.f) - mean * mean;
        float rstd = rsqrtf(var + EPSf);
        #pragma unroll
        for (int i = 0; i < 2; i++) {
            int j = tid + i * 256;
            d.dst[base + j] = d.scale * ((x[i] - mean) * rstd * d.g[j] + d.b[j]);
        }
    } else {
        #pragma unroll
        for (int i = 0; i < 2; i++) {
            int j = tid + i * 256;
            d.dst[base + j] = d.scale * x[i];
        }
    }
}

// ---------------- final: sum remaining outs + LayerNorm ----------------
__global__ __launch_bounds__(256) void final_kernel(const float* out_g, const float* out_beta,
                                                    float* out) {
    int row = blockIdx.x;
    int tid = threadIdx.x;
    int mask = g_rem_mask;
    size_t base = (size_t)row * D;
    float x[2];
    #pragma unroll
    for (int i = 0; i < 2; i++) {
        int j = tid + i * 256;
        float s = 0.f;
        for (int n = 0; n < 8; n++)
            if ((mask >> n) & 1) s += g_outs[n][base + j];
        x[i] = s;
    }
    __shared__ float rs[256], rq[256];
    rs[tid] = x[0] + x[1];
    rq[tid] = x[0] * x[0] + x[1] * x[1];
    __syncthreads();
    for (int off = 128; off > 0; off >>= 1) {
        if (tid < off) { rs[tid] += rs[tid + off]; rq[tid] += rq[tid + off]; }
        __syncthreads();
    }
    float mean = rs[0] * (1.f / 512.f);
    float var = rq[0] * (1.f / 512.f) - mean * mean;
    float rstd = rsqrtf(var + EPSf);
    #pragma unroll
    for (int i = 0; i < 2; i++) {
        int j = tid + i * 256;
        out[base + j] = (x[i] - mean) * rstd * out_g[j] + out_beta[j];
    }
}

// ---------------- launch ----------------
extern "C" void kernel_launch(void* const* d_in, const int* in_sizes, int n_in,
                              void* d_out, int out_size) {
    const float* inpute   = (const float*)d_in[0];
    const float* inputo   = (const float*)d_in[1];
    const float* node_p   = (const float*)d_in[2];
    const float* edge_p   = (const float*)d_in[3];
    const float* edge_W   = (const float*)d_in[4];
    const float* edge_b   = (const float*)d_in[5];
    const float* edge_g   = (const float*)d_in[6];
    const float* edge_bet = (const float*)d_in[7];
    const float* node_W   = (const float*)d_in[8];
    const float* node_b   = (const float*)d_in[9];
    const float* node_g   = (const float*)d_in[10];
    const float* node_bet = (const float*)d_in[11];
    const float* out_g    = (const float*)d_in[12];
    const float* out_bet  = (const float*)d_in[13];
    float* out = (float*)d_out;

    routing_kernel<<<1, 1>>>(inpute, inputo, node_p, edge_p,
                             edge_W, edge_b, edge_g, edge_bet,
                             node_W, node_b, node_g, node_bet);

    dim3 ggrid(D / BN, NTOK / BM);   // (8, 32)
    for (int c = 0; c < 8; c++) {
        for (int w = 0; w < 3; w++) {
            gemm_slot<<<ggrid, 256>>>(c * 7 + w);
            copy_slot<<<512, 256>>>(c * 3 + w);
        }
        gemm_slot<<<ggrid, 256>>>(c * 7 + 3);
        gemm_slot<<<ggrid, 256>>>(c * 7 + 4);
        gemm_slot<<<ggrid, 256>>>(c * 7 + 5);
        attn_slot<<<dim3(32, 128), 256>>>(c);
        gemm_slot<<<ggrid, 256>>>(c * 7 + 6);
        elem_node_kernel<<<NTOK, 256>>>(c);
    }
    final_kernel<<<NTOK, 256>>>(out_g, out_bet, out);
}

// round 7
// speedup vs baseline: 1.4087x; 1.1437x over previous
#include <cuda_runtime.h>
#include <cuda_bf16.h>
#include <math.h>
#include <stdint.h>

#define D       512
#define NTOK    4096      // B*SLEN = 4*1024
#define NNODn   8
#define NEDGEn  34
#define EPSf    1e-6f

// GEMM tile
#define BM 128
#define BN 64
#define BK 32        // k per stage

// ---------------- scratch buffers (device globals; no allocation allowed) ----------
__device__ float g_outs[8][NTOK * D];
__device__ float g_q[NTOK * D];
__device__ float g_k[NTOK * D];
__device__ float g_v[NTOK * D];
__device__ float g_t1[NTOK * D];
__device__ float g_t2[NTOK * D];
__device__ float g_t3[NTOK * D];
__device__ float g_t4[NTOK * D];

// ---------------- descriptors ----------------
struct GemmDesc {
    int active;
    int pre_mode;    // 0 none, 1 LN(A), 2 relu(A)
    int epi_act;     // 0 none, 1 relu, 2 gelu
    int accumulate;  // 1: C += result
    const float *A, *W, *bias, *lng, *lnb, *mult, *residual;
    float scale;
    float *C;
};
struct CopyDesc { int active; const float* src; float* dst; float scale; };
struct ElemDesc {
    int active; int opcode;   // 2,4,6,7
    const float *q, *k, *v, *g, *b;
    float scale; float* dst;
};

__device__ GemmDesc g_gd[56];   // node*7 + {EQ,EK,EV,G1,G2,G3,G4}
__device__ CopyDesc g_cd[24];   // node*3 + {q,k,v}
__device__ ElemDesc g_ed[8];
__device__ int g_attn_on[8];
__device__ int g_rem_mask;

// ---------------- bf16 split helpers ----------------
// pack (x0, x1) consecutive: .x = hi bf16x2, .y = lo bf16x2
__device__ __forceinline__ uint2 split_pair(float x0, float x1) {
    __nv_bfloat162 hh;
    asm("cvt.rn.bf16x2.f32 %0, %1, %2;" : "=r"(*(uint32_t*)&hh) : "f"(x1), "f"(x0));
    float l0 = x0 - __bfloat162float(hh.x);
    float l1 = x1 - __bfloat162float(hh.y);
    uint32_t ll;
    asm("cvt.rn.bf16x2.f32 %0, %1, %2;" : "=r"(ll) : "f"(l1), "f"(l0));
    uint2 r;
    r.x = *(uint32_t*)&hh;
    r.y = ll;
    return r;
}

__device__ __forceinline__ void mma_bf16(float* c, const uint32_t* a, const uint32_t* b) {
    asm volatile(
        "mma.sync.aligned.m16n8k16.row.col.f32.bf16.bf16.f32 "
        "{%0,%1,%2,%3}, {%4,%5,%6,%7}, {%8,%9}, {%0,%1,%2,%3};"
        : "+f"(c[0]), "+f"(c[1]), "+f"(c[2]), "+f"(c[3])
        : "r"(a[0]), "r"(a[1]), "r"(a[2]), "r"(a[3]),
          "r"(b[0]), "r"(b[1]));
}

__device__ __forceinline__ void ldsm_x4(uint32_t* r, uint32_t addr) {
    asm volatile("ldmatrix.sync.aligned.m8n8.x4.shared.b16 {%0,%1,%2,%3}, [%4];"
                 : "=r"(r[0]), "=r"(r[1]), "=r"(r[2]), "=r"(r[3]) : "r"(addr));
}
__device__ __forceinline__ void ldsm_x4_trans(uint32_t* r, uint32_t addr) {
    asm volatile("ldmatrix.sync.aligned.m8n8.x4.trans.shared.b16 {%0,%1,%2,%3}, [%4];"
                 : "=r"(r[0]), "=r"(r[1]), "=r"(r[2]), "=r"(r[3]) : "r"(addr));
}

// ---------------- small helpers ----------------
__device__ __forceinline__ float gelu_f(float x) {
    const float k0 = 0.7978845608028654f;
    float x3 = x * x * x;
    return 0.5f * x * (1.f + tanhf(k0 * (x + 0.044715f * x3)));
}

__device__ float selw_masked(const float* l, int L, int mask5, int sel) {
    float mx = -1e30f;
    for (int i = 0; i < L; i++) { if (mask5 && i < 5) continue; if (l[i] > mx) mx = l[i]; }
    float s = 0.f;
    for (int i = 0; i < L; i++) { if (mask5 && i < 5) continue; s += expf(l[i] - mx); }
    return expf(l[sel] - mx) / s;
}

__device__ void set_gd(int slot, const float* A, const float* W, const float* bias,
                       int pre, const float* lng, const float* lnb,
                       int epi, const float* mult, const float* residual,
                       float scale, float* C, int accum) {
    GemmDesc& g = g_gd[slot];
    g.active = 1; g.A = A; g.W = W; g.bias = bias;
    g.pre_mode = pre; g.lng = lng; g.lnb = lnb;
    g.epi_act = epi; g.mult = mult; g.residual = residual;
    g.scale = scale; g.C = C; g.accumulate = accum;
}

// Fill an edge slot; returns consumed input node index inn (-2..7)
__device__ int fill_edge(int node, int which, int sel, float w, int lind, int snode,
                         const float* const* bufs,
                         const float* eW, const float* eb, const float* eg, const float* ebe,
                         float* dst) {
    int se = sel / 5, op = sel % 5;
    int inn = (se == 0) ? -2 : (snode + se);
    int e = lind + se;
    const float* src = bufs[inn + 2];
    if (op == 4) {
        CopyDesc& cd = g_cd[node * 3 + which];
        cd.active = 1; cd.src = src; cd.dst = dst; cd.scale = w;
    } else {
        set_gd(node * 7 + which,
               src, eW + (size_t)e * D * D, eb + e * D,
               (op <= 2) ? 1 : 0, eg + e * D, ebe + e * D,
               (op == 0) ? 1 : ((op == 1) ? 2 : 0),
               nullptr, nullptr, w, dst, 0);
    }
    return inn;
}

// ---------------- routing kernel: computes routes + writes all descriptors ----------
__global__ void routing_kernel(const float* inpute, const float* inputo,
                               const float* node_p, const float* edge_p,
                               const float* edge_W, const float* edge_b,
                               const float* edge_g, const float* edge_beta,
                               const float* node_W, const float* node_b,
                               const float* node_g, const float* node_beta) {
    if (threadIdx.x != 0 || blockIdx.x != 0) return;

    const float* bufs[10];
    bufs[0] = inpute; bufs[1] = inputo;
    for (int i = 0; i < 8; i++) bufs[2 + i] = g_outs[i];

    for (int i = 0; i < 56; i++) g_gd[i].active = 0;
    for (int i = 0; i < 24; i++) g_cd[i].active = 0;
    for (int i = 0; i < 8; i++) { g_ed[i].active = 0; g_attn_on[i] = 0; }

    int processed = 0;
    int lind = 0;
    for (int c = 0; c < 8; c++) {
        int nsrc = (c + 2 < 5) ? (c + 2) : 5;
        int snode = c - nsrc;
        int L = nsrc * 5;
        float ep0[25], ep1[25], ep2[25];
        for (int s = 0; s < nsrc; s++)
            for (int j = 0; j < 5; j++) {
                int e = lind + s;
                ep0[s * 5 + j] = edge_p[(0 * NEDGEn + e) * 5 + j];
                ep1[s * 5 + j] = edge_p[(1 * NEDGEn + e) * 5 + j];
                ep2[s * 5 + j] = edge_p[(2 * NEDGEn + e) * 5 + j];
            }
        // node activation argmax + softmax weight
        int nact = 0; float bb = node_p[c * 8];
        for (int i = 1; i < 8; i++) { float x = node_p[c * 8 + i]; if (x > bb) { bb = x; nact = i; } }
        float aw;
        { float sum = 0.f; for (int i = 0; i < 8; i++) sum += expf(node_p[c * 8 + i] - bb);
          aw = expf(node_p[c * 8 + nact] - bb) / sum; }

        // q selection: first 5 masked
        int qsel = 5; float qb = ep0[5];
        for (int i = 6; i < L; i++) if (ep0[i] > qb) { qb = ep0[i]; qsel = i; }
        float wq = selw_masked(ep0, L, 1, qsel);

        int ksel = -1, vsel = -1;
        float wk = 0.f, wv = 0.f;
        int ktype = 0;
        if (nact < 7) {
            int km = (nact > 0) ? 1 : 0;
            int start = km ? 5 : 0;
            ksel = start; float kb = ep1[start];
            for (int i = start + 1; i < L; i++) if (ep1[i] > kb) { kb = ep1[i]; ksel = i; }
            wk = selw_masked(ep1, L, km, ksel);
            ktype = (ksel / 5 == 0) ? -2 : -1;
            if (nact < 5) {
                if (nact == 0 && ktype == -2) {
                    vsel = 0; float vb = ep2[0];
                    for (int i = 1; i < 5; i++) if (ep2[i] > vb) { vb = ep2[i]; vsel = i; }
                    wv = selw_masked(ep2, 5, 0, vsel);
                } else {
                    int vm = km;
                    int vstart = vm ? 5 : 0;
                    vsel = vstart; float vb = ep2[vstart];
                    for (int i = vstart + 1; i < L; i++) if (ep2[i] > vb) { vb = ep2[i]; vsel = i; }
                    wv = selw_masked(ep2, L, vm, vsel);
                }
            }
        }

        // edge descriptors
        float* outc = g_outs[c];
        int inn;
        inn = fill_edge(c, 0, qsel, wq, lind, snode, bufs, edge_W, edge_b, edge_g, edge_beta, g_q);
        processed |= 1 << (inn + 2);
        if (nact < 7) {
            inn = fill_edge(c, 1, ksel, wk, lind, snode, bufs, edge_W, edge_b, edge_g, edge_beta, g_k);
            processed |= 1 << (inn + 2);
        }
        if (nact < 5) {
            inn = fill_edge(c, 2, vsel, wv, lind, snode, bufs, edge_W, edge_b, edge_g, edge_beta, g_v);
            processed |= 1 << (inn + 2);
        }

        // node descriptors
        const float* nw  = node_W + (size_t)c * 4 * D * D;
        const float* nbv = node_b + (size_t)c * 4 * D;
        const float* ngv = node_g + (size_t)c * D;
        const float* nbe = node_beta + (size_t)c * D;
        int s3 = c * 7 + 3, s4 = c * 7 + 4, s5 = c * 7 + 5, s6 = c * 7 + 6;

        if (nact == 0) {
            set_gd(s3, g_q, nw,             nbv,         1, ngv, nbe, 0, nullptr, nullptr, 1.f, g_t1, 0);
            set_gd(s4, g_k, nw + D * D,     nbv + D,     0, nullptr, nullptr, 0, nullptr, nullptr, 1.f, g_t2, 0);
            set_gd(s5, g_v, nw + 2 * D * D, nbv + 2 * D, 0, nullptr, nullptr, 0, nullptr, nullptr, 1.f, g_t3, 0);
            g_attn_on[c] = 1;
            set_gd(s6, g_t4, nw + 3 * D * D, nbv + 3 * D, 0, nullptr, nullptr, 0, nullptr, g_q, aw, outc, 0);
        } else if (nact == 1) {
            set_gd(s3, g_q, nw,         nbv,     0, nullptr, nullptr, 2, nullptr, nullptr, 1.f, g_t1, 0);
            set_gd(s4, g_k, nw + D * D, nbv + D, 0, nullptr, nullptr, 0, g_t1, nullptr, 1.f, g_t4, 0);
            set_gd(s6, g_t4, nw + 3 * D * D, nbv + 3 * D, 0, nullptr, nullptr, 0, nullptr, g_q, aw, outc, 0);
        } else if (nact == 3) {
            set_gd(s3, g_q, nw,             nullptr, 0, nullptr, nullptr, 0, nullptr, nullptr, 1.f, g_t1, 0);
            set_gd(s4, g_k, nw + D * D,     nullptr, 0, nullptr, nullptr, 0, nullptr, nullptr, 1.f, g_t1, 1);
            set_gd(s5, g_v, nw + 2 * D * D, nullptr, 0, nullptr, nullptr, 0, nullptr, nullptr, 1.f, g_t1, 1);
            set_gd(s6, g_t1, nw + 3 * D * D, nbv + 3 * D, 2, nullptr, nullptr, 0, nullptr, g_q, aw, outc, 0);
        } else if (nact == 5) {
            set_gd(s4, g_k, nw + D * D, nbv + D, 0, nullptr, nullptr, 2, nullptr, g_q, aw, outc, 0);
        } else { // 2, 4, 6, 7 elementwise
            ElemDesc& e = g_ed[c];
            e.active = 1; e.opcode = nact;
            e.q = g_q; e.k = g_k; e.v = g_v;
            e.g = ngv; e.b = nbe; e.scale = aw; e.dst = outc;
        }
        lind += nsrc;
    }
    int rem = 0;
    for (int n = 0; n < 8; n++)
        if (!((processed >> (n + 2)) & 1)) rem |= 1 << n;
    g_rem_mask = rem;
}

// ---------------- GEMM slot kernel: bf16 split-2, ldmatrix + swizzled tiles -------
// C[NTOK,D] = epi( pre(A)[NTOK,D] @ W[D,D] + bias ) (*mult)(+residual)(*scale)
// BM=128, BN=64, BK=32; 8 warps 4(M)x2(N); warp tile 32x32 = 2 m16 x 4 n8.
// A tiles: [128 rows][32 k] bf16, 4x16B chunks/row, chunk swizzle c^((row>>1)&3)
// B tiles: [32 k rows][64 n] bf16, 8x16B chunks/row, chunk swizzle c^(row&7)
__global__ __launch_bounds__(256) void gemm_slot(int slot) {
    GemmDesc d = g_gd[slot];
    if (!d.active) return;

    __shared__ uint4 sAhi[128 * 4], sAlo[128 * 4];
    __shared__ uint2 sBhi[32 * 16], sBlo[32 * 16];
    __shared__ float s_mean[BM], s_rstd[BM];

    uint32_t aHiB = (uint32_t)__cvta_generic_to_shared(sAhi);
    uint32_t aLoB = (uint32_t)__cvta_generic_to_shared(sAlo);
    uint32_t bHiB = (uint32_t)__cvta_generic_to_shared(sBhi);
    uint32_t bLoB = (uint32_t)__cvta_generic_to_shared(sBlo);

    int tid = threadIdx.x;
    int m0 = blockIdx.y * BM;
    int n0 = blockIdx.x * BN;

    if (d.pre_mode == 1) {
        __shared__ float red_s[256], red_q[256];
        int r = tid >> 1, p = tid & 1;
        const float4* row = (const float4*)(d.A + (size_t)(m0 + r) * D + p * 256);
        float s = 0.f, q = 0.f;
        #pragma unroll
        for (int i = 0; i < 64; i++) {
            float4 v = row[i];
            s += v.x + v.y + v.z + v.w;
            q += v.x * v.x + v.y * v.y + v.z * v.z + v.w * v.w;
        }
        red_s[tid] = s; red_q[tid] = q;
        __syncthreads();
        if (p == 0) {
            float S = red_s[tid] + red_s[tid + 1];
            float Q = red_q[tid] + red_q[tid + 1];
            float m = S * (1.f / 512.f);
            float var = Q * (1.f / 512.f) - m * m;
            s_mean[r] = m; s_rstd[r] = rsqrtf(var + EPSf);
        }
        __syncthreads();
    }

    int warp = tid >> 5, lane = tid & 31;
    int g = lane >> 2, t = lane & 3;
    int wM = (warp >> 1) * 32;    // 4 warps along M
    int wN = (warp & 1) * 32;     // 2 warps along N

    // staging maps
    int arow = tid & 127;          // A row
    int ahalf = tid >> 7;          // k half (0: k0-15, 1: k16-31)
    int bk = tid >> 3;             // B k row 0..31
    int bq = tid & 7;              // B float4 quad

    float acc[2][4][4];
    #pragma unroll
    for (int a = 0; a < 2; a++)
        #pragma unroll
        for (int bb = 0; bb < 4; bb++)
            #pragma unroll
            for (int cc = 0; cc < 4; cc++) acc[a][bb][cc] = 0.f;

    float4 aval[4], bval[2];
    {
        const float* ap = d.A + (size_t)(m0 + arow) * D + ahalf * 16;
        #pragma unroll
        for (int i = 0; i < 4; i++) aval[i] = *(const float4*)(ap + i * 4);
        const float* wp = d.W + (size_t)bk * D + n0;
        bval[0] = *(const float4*)(wp + bq * 4);
        bval[1] = *(const float4*)(wp + bq * 4 + 32);
    }

    for (int kt = 0; kt < D / BK; kt++) {
        // ---- stage A ----
        {
            float x[16];
            #pragma unroll
            for (int i = 0; i < 4; i++) {
                x[i * 4 + 0] = aval[i].x; x[i * 4 + 1] = aval[i].y;
                x[i * 4 + 2] = aval[i].z; x[i * 4 + 3] = aval[i].w;
            }
            if (d.pre_mode == 1) {
                float mn = s_mean[arow], rs = s_rstd[arow];
                int kg = kt * BK + ahalf * 16;
                #pragma unroll
                for (int i = 0; i < 16; i++)
                    x[i] = (x[i] - mn) * rs * d.lng[kg + i] + d.lnb[kg + i];
            } else if (d.pre_mode == 2) {
                #pragma unroll
                for (int i = 0; i < 16; i++) x[i] = fmaxf(x[i], 0.f);
            }
            uint2 sp[8];
            #pragma unroll
            for (int i = 0; i < 8; i++) sp[i] = split_pair(x[2 * i], x[2 * i + 1]);
            int sw = (arow >> 1) & 3;
            int c0 = ahalf * 2, c1 = c0 + 1;
            sAhi[arow * 4 + (c0 ^ sw)] = make_uint4(sp[0].x, sp[1].x, sp[2].x, sp[3].x);
            sAhi[arow * 4 + (c1 ^ sw)] = make_uint4(sp[4].x, sp[5].x, sp[6].x, sp[7].x);
            sAlo[arow * 4 + (c0 ^ sw)] = make_uint4(sp[0].y, sp[1].y, sp[2].y, sp[3].y);
            sAlo[arow * 4 + (c1 ^ sw)] = make_uint4(sp[4].y, sp[5].y, sp[6].y, sp[7].y);
        }
        // ---- stage B ----
        {
            #pragma unroll
            for (int jj = 0; jj < 2; jj++) {
                float4 wv = bval[jj];
                uint2 s1 = split_pair(wv.x, wv.y);
                uint2 s2 = split_pair(wv.z, wv.w);
                int nq = bq + jj * 8;           // float4 index along n (0..15)
                int c = nq >> 1;                // 16B chunk (0..7)
                int h8 = nq & 1;                // 8B half within chunk
                int slot2 = bk * 16 + ((c ^ (bk & 7)) << 1) + h8;
                sBhi[slot2] = make_uint2(s1.x, s2.x);
                sBlo[slot2] = make_uint2(s1.y, s2.y);
            }
        }
        __syncthreads();
        // ---- prefetch next stage ----
        if (kt + 1 < D / BK) {
            int kb = (kt + 1) * BK;
            const float* ap = d.A + (size_t)(m0 + arow) * D + kb + ahalf * 16;
            #pragma unroll
            for (int i = 0; i < 4; i++) aval[i] = *(const float4*)(ap + i * 4);
            const float* wp = d.W + (size_t)(kb + bk) * D + n0;
            bval[0] = *(const float4*)(wp + bq * 4);
            bval[1] = *(const float4*)(wp + bq * 4 + 32);
        }
        // ---- compute: 2 k16 steps ----
        #pragma unroll
        for (int kb = 0; kb < 2; kb++) {
            uint32_t ahi[2][4], alo[2][4];
            #pragma unroll
            for (int mt = 0; mt < 2; mt++) {
                int row = wM + mt * 16 + (lane & 15);
                int c = kb * 2 + (lane >> 4);
                uint32_t off = (uint32_t)(row * 4 + (c ^ ((row >> 1) & 3))) * 16;
                ldsm_x4(ahi[mt], aHiB + off);
                ldsm_x4(alo[mt], aLoB + off);
            }
            uint32_t bh[4][2], bl[4][2];
            #pragma unroll
            for (int ng = 0; ng < 2; ng++) {
                int krow = kb * 16 + 8 * ((lane >> 3) & 1) + (lane & 7);
                int nch = (wN + ng * 16 + 8 * (lane >> 4)) >> 3;
                uint32_t off = (uint32_t)krow * 128 + (uint32_t)((nch ^ (krow & 7)) << 4);
                uint32_t r[4];
                ldsm_x4_trans(r, bHiB + off);
                bh[ng * 2][0] = r[0]; bh[ng * 2][1] = r[1];
                bh[ng * 2 + 1][0] = r[2]; bh[ng * 2 + 1][1] = r[3];
                ldsm_x4_trans(r, bLoB + off);
                bl[ng * 2][0] = r[0]; bl[ng * 2][1] = r[1];
                bl[ng * 2 + 1][0] = r[2]; bl[ng * 2 + 1][1] = r[3];
            }
            #pragma unroll
            for (int mt = 0; mt < 2; mt++)
                #pragma unroll
                for (int nt = 0; nt < 4; nt++) {
                    mma_bf16(acc[mt][nt], ahi[mt], bh[nt]);
                    mma_bf16(acc[mt][nt], ahi[mt], bl[nt]);
                    mma_bf16(acc[mt][nt], alo[mt], bh[nt]);
                }
        }
        __syncthreads();
    }

    // epilogue
    #pragma unroll
    for (int mt = 0; mt < 2; mt++)
        #pragma unroll
        for (int nt = 0; nt < 4; nt++) {
            int m = m0 + wM + mt * 16 + g;
            int n = n0 + wN + nt * 8 + 2 * t;
            float b0v = 0.f, b1v = 0.f;
            if (d.bias) { b0v = d.bias[n]; b1v = d.bias[n + 1]; }
            #pragma unroll
            for (int rr = 0; rr < 2; rr++) {
                int mr = m + rr * 8;
                float x0 = acc[mt][nt][rr * 2 + 0] + b0v;
                float x1 = acc[mt][nt][rr * 2 + 1] + b1v;
                if (d.epi_act == 1) { x0 = fmaxf(x0, 0.f); x1 = fmaxf(x1, 0.f); }
                else if (d.epi_act == 2) { x0 = gelu_f(x0); x1 = gelu_f(x1); }
                if (d.mult) {
                    float2 mv = *(const float2*)(d.mult + (size_t)mr * D + n);
                    x0 *= mv.x; x1 *= mv.y;
                }
                if (d.residual) {
                    float2 rv = *(const float2*)(d.residual + (size_t)mr * D + n);
                    x0 += rv.x; x1 += rv.y;
                }
                x0 *= d.scale; x1 *= d.scale;
                if (d.accumulate) {
                    float2 cv = *(const float2*)(d.C + (size_t)mr * D + n);
                    x0 += cv.x; x1 += cv.y;
                }
                *(float2*)(d.C + (size_t)mr * D + n) = make_float2(x0, x1);
            }
        }
}

// ---------------- edge op4 copy-scale ----------------
__global__ void copy_slot(int slot) {
    CopyDesc d = g_cd[slot];
    if (!d.active) return;
    int i = blockIdx.x * blockDim.x + threadIdx.x;
    int stride = gridDim.x * blockDim.x;
    const float4* src = (const float4*)d.src;
    float4* dst = (float4*)d.dst;
    for (; i < NTOK * D / 4; i += stride) {
        float4 v = src[i];
        v.x *= d.scale; v.y *= d.scale; v.z *= d.scale; v.w *= d.scale;
        dst[i] = v;
    }
}

// ---------------- attention (act 0): one warp per query row, online softmax ------
__global__ __launch_bounds__(256) void attn_slot(int c) {
    if (!g_attn_on[c]) return;
    int warp = threadIdx.x >> 5, lane = threadIdx.x & 31;
    int bh = blockIdx.x;            // 0..31
    int b = bh >> 3, h = bh & 7;
    int s = blockIdx.y * 8 + warp;  // 0..1023

    const float* qrow = g_t1 + (size_t)((b << 10) + s) * D + h * 64 + lane * 2;
    float q0 = qrow[0], q1 = qrow[1];
    const float* kbase = g_t2 + (size_t)(b << 10) * D + h * 64 + lane * 2;
    const float* vbase = g_t3 + (size_t)(b << 10) * D + h * 64 + lane * 2;

    float m = -1e30f, l = 0.f, a0 = 0.f, a1 = 0.f;
    for (int sk = 0; sk < 1024; sk++) {
        float2 kk = *(const float2*)(kbase + (size_t)sk * D);
        float p = q0 * kk.x + q1 * kk.y;
        p += __shfl_xor_sync(0xFFFFFFFFu, p, 16);
        p += __shfl_xor_sync(0xFFFFFFFFu, p, 8);
        p += __shfl_xor_sync(0xFFFFFFFFu, p, 4);
        p += __shfl_xor_sync(0xFFFFFFFFu, p, 2);
        p += __shfl_xor_sync(0xFFFFFFFFu, p, 1);
        float dot = p * 0.125f;
        float mn = fmaxf(m, dot);
        float corr = __expf(m - mn);
        float w = __expf(dot - mn);
        float2 vv = *(const float2*)(vbase + (size_t)sk * D);
        l = l * corr + w;
        a0 = a0 * corr + w * vv.x;
        a1 = a1 * corr + w * vv.y;
        m = mn;
    }
    float inv = 1.f / l;
    float* orow = g_t4 + (size_t)((b << 10) + s) * D + h * 64 + lane * 2;
    orow[0] = a0 * inv;
    orow[1] = a1 * inv;
}

// ---------------- elementwise node ops (acts 2,4,6,7) ----------------
__global__ __launch_bounds__(256) void elem_node_kernel(int c) {
    ElemDesc d = g_ed[c];
    if (!d.active) return;
    int row = blockIdx.x;
    int tid = threadIdx.x;
    size_t base = (size_t)row * D;
    float x[2];
    #pragma unroll
    for (int i = 0; i < 2; i++) {
        int j = tid + i * 256;
        float qv = d.q[base + j];
        if (d.opcode == 2) x[i] = qv + d.k[base + j] + d.v[base + j];
        else if (d.opcode == 4) {
            float kv = d.k[base + j];
            x[i] = qv * (1.f / (1.f + expf(-kv))) + d.v[base + j];
        }
        else if (d.opcode == 6) x[i] = qv + d.k[base + j];
        else x[i] = qv; // 7
    }
    if (d.opcode == 2 || d.opcode == 7) {
        __shared__ float rs[256], rq[256];
        rs[tid] = x[0] + x[1];
        rq[tid] = x[0] * x[0] + x[1] * x[1];
        __syncthreads();
        for (int off = 128; off > 0; off >>= 1) {
            if (tid < off) { rs[tid] += rs[tid + off]; rq[tid] += rq[tid + off]; }
            __syncthreads();
        }
        float mean = rs[0] * (1.f / 512.f);
        float var = rq[0] * (1.f / 512.f) - mean * mean;
        float rstd = rsqrtf(var + EPSf);
        #pragma unroll
        for (int i = 0; i < 2; i++) {
            int j = tid + i * 256;
            d.dst[base + j] = d.scale * ((x[i] - mean) * rstd * d.g[j] + d.b[j]);
        }
    } else {
        #pragma unroll
        for (int i = 0; i < 2; i++) {
            int j = tid + i * 256;
            d.dst[base + j] = d.scale * x[i];
        }
    }
}

// ---------------- final: sum remaining outs + LayerNorm ----------------
__global__ __launch_bounds__(256) void final_kernel(const float* out_g, const float* out_beta,
                                                    float* out) {
    int row = blockIdx.x;
    int tid = threadIdx.x;
    int mask = g_rem_mask;
    size_t base = (size_t)row * D;
    float x[2];
    #pragma unroll
    for (int i = 0; i < 2; i++) {
        int j = tid + i * 256;
        float s = 0.f;
        for (int n = 0; n < 8; n++)
            if ((mask >> n) & 1) s += g_outs[n][base + j];
        x[i] = s;
    }
    __shared__ float rs[256], rq[256];
    rs[tid] = x[0] + x[1];
    rq[tid] = x[0] * x[0] + x[1] * x[1];
    __syncthreads();
    for (int off = 128; off > 0; off >>= 1) {
        if (tid < off) { rs[tid] += rs[tid + off]; rq[tid] += rq[tid + off]; }
        __syncthreads();
    }
    float mean = rs[0] * (1.f / 512.f);
    float var = rq[0] * (1.f / 512.f) - mean * mean;
    float rstd = rsqrtf(var + EPSf);
    #pragma unroll
    for (int i = 0; i < 2; i++) {
        int j = tid + i * 256;
        out[base + j] = (x[i] - mean) * rstd * out_g[j] + out_beta[j];
    }
}

// ---------------- launch ----------------
extern "C" void kernel_launch(void* const* d_in, const int* in_sizes, int n_in,
                              void* d_out, int out_size) {
    const float* inpute   = (const float*)d_in[0];
    const float* inputo   = (const float*)d_in[1];
    const float* node_p   = (const float*)d_in[2];
    const float* edge_p   = (const float*)d_in[3];
    const float* edge_W   = (const float*)d_in[4];
    const float* edge_b   = (const float*)d_in[5];
    const float* edge_g   = (const float*)d_in[6];
    const float* edge_bet = (const float*)d_in[7];
    const float* node_W   = (const float*)d_in[8];
    const float* node_b   = (const float*)d_in[9];
    const float* node_g   = (const float*)d_in[10];
    const float* node_bet = (const float*)d_in[11];
    const float* out_g    = (const float*)d_in[12];
    const float* out_bet  = (const float*)d_in[13];
    float* out = (float*)d_out;

    routing_kernel<<<1, 1>>>(inpute, inputo, node_p, edge_p,
                             edge_W, edge_b, edge_g, edge_bet,
                             node_W, node_b, node_g, node_bet);

    dim3 ggrid(D / BN, NTOK / BM);   // (8, 32)
    for (int c = 0; c < 8; c++) {
        for (int w = 0; w < 3; w++) {
            gemm_slot<<<ggrid, 256>>>(c * 7 + w);
            copy_slot<<<512, 256>>>(c * 3 + w);
        }
        gemm_slot<<<ggrid, 256>>>(c * 7 + 3);
        gemm_slot<<<ggrid, 256>>>(c * 7 + 4);
        gemm_slot<<<ggrid, 256>>>(c * 7 + 5);
        attn_slot<<<dim3(32, 128), 256>>>(c);
        gemm_slot<<<ggrid, 256>>>(c * 7 + 6);
        elem_node_kernel<<<NTOK, 256>>>(c);
    }
    final_kernel<<<NTOK, 256>>>(out_g, out_bet, out);
}

// round 12
// speedup vs baseline: 2.6248x; 1.8633x over previous
#include <cuda_runtime.h>
#include <cuda_bf16.h>
#include <math.h>
#include <stdint.h>

#define D       512
#define NTOK    4096      // B*SLEN = 4*1024
#define NNODn   8
#define NEDGEn  34
#define EPSf    1e-6f

// GEMM tile
#define BM 128
#define BN 64
#define BK 32        // k per stage

// ---------------- scratch buffers (device globals; no allocation allowed) ----------
__device__ float g_outs[8][NTOK * D];
__device__ float g_q[NTOK * D];
__device__ float g_k[NTOK * D];
__device__ float g_v[NTOK * D];
__device__ float g_t1[NTOK * D];
__device__ float g_t2[NTOK * D];
__device__ float g_t3[NTOK * D];
__device__ float g_t4[NTOK * D];

// pre-split bf16 operand buffers (uint4 = 8 bf16 = one 16B ldmatrix chunk)
__device__ uint4 g_Ahi4[NTOK * 64];     // [row][64 chunks]
__device__ uint4 g_Alo4[NTOK * 64];
__device__ uint4 g_Whi4[D * 64];        // [k][64 chunks] (k-major, same as W)
__device__ uint4 g_Wlo4[D * 64];

// ---------------- descriptors ----------------
struct GemmDesc {
    int active;
    int pre_mode;    // 0 none, 1 LN(A), 2 relu(A)
    int epi_act;     // 0 none, 1 relu, 2 gelu
    int accumulate;  // 1: C += result
    const float *A, *W, *bias, *lng, *lnb, *mult, *residual;
    float scale;
    float *C;
};
struct CopyDesc { int active; const float* src; float* dst; float scale; };
struct ElemDesc {
    int active; int opcode;   // 2,4,6,7
    const float *q, *k, *v, *g, *b;
    float scale; float* dst;
};

__device__ GemmDesc g_gd[56];   // node*7 + {EQ,EK,EV,G1,G2,G3,G4}
__device__ CopyDesc g_cd[24];   // node*3 + {q,k,v}
__device__ ElemDesc g_ed[8];
__device__ int g_attn_on[8];
__device__ int g_rem_mask;

// ---------------- bf16 split helpers ----------------
// pack (x0, x1) consecutive: .x = hi bf16x2, .y = lo bf16x2
__device__ __forceinline__ uint2 split_pair(float x0, float x1) {
    __nv_bfloat162 hh;
    asm("cvt.rn.bf16x2.f32 %0, %1, %2;" : "=r"(*(uint32_t*)&hh) : "f"(x1), "f"(x0));
    float l0 = x0 - __bfloat162float(hh.x);
    float l1 = x1 - __bfloat162float(hh.y);
    uint32_t ll;
    asm("cvt.rn.bf16x2.f32 %0, %1, %2;" : "=r"(ll) : "f"(l1), "f"(l0));
    uint2 r;
    r.x = *(uint32_t*)&hh;
    r.y = ll;
    return r;
}

__device__ __forceinline__ void mma_bf16(float* c, const uint32_t* a, const uint32_t* b) {
    asm volatile(
        "mma.sync.aligned.m16n8k16.row.col.f32.bf16.bf16.f32 "
        "{%0,%1,%2,%3}, {%4,%5,%6,%7}, {%8,%9}, {%0,%1,%2,%3};"
        : "+f"(c[0]), "+f"(c[1]), "+f"(c[2]), "+f"(c[3])
        : "r"(a[0]), "r"(a[1]), "r"(a[2]), "r"(a[3]),
          "r"(b[0]), "r"(b[1]));
}

__device__ __forceinline__ void ldsm_x4(uint32_t* r, uint32_t addr) {
    asm volatile("ldmatrix.sync.aligned.m8n8.x4.shared.b16 {%0,%1,%2,%3}, [%4];"
                 : "=r"(r[0]), "=r"(r[1]), "=r"(r[2]), "=r"(r[3]) : "r"(addr));
}
__device__ __forceinline__ void ldsm_x4_trans(uint32_t* r, uint32_t addr) {
    asm volatile("ldmatrix.sync.aligned.m8n8.x4.trans.shared.b16 {%0,%1,%2,%3}, [%4];"
                 : "=r"(r[0]), "=r"(r[1]), "=r"(r[2]), "=r"(r[3]) : "r"(addr));
}

// ---------------- small helpers ----------------
__device__ __forceinline__ float gelu_f(float x) {
    const float k0 = 0.7978845608028654f;
    float x3 = x * x * x;
    return 0.5f * x * (1.f + tanhf(k0 * (x + 0.044715f * x3)));
}

__device__ float selw_masked(const float* l, int L, int mask5, int sel) {
    float mx = -1e30f;
    for (int i = 0; i < L; i++) { if (mask5 && i < 5) continue; if (l[i] > mx) mx = l[i]; }
    float s = 0.f;
    for (int i = 0; i < L; i++) { if (mask5 && i < 5) continue; s += expf(l[i] - mx); }
    return expf(l[sel] - mx) / s;
}

__device__ void set_gd(int slot, const float* A, const float* W, const float* bias,
                       int pre, const float* lng, const float* lnb,
                       int epi, const float* mult, const float* residual,
                       float scale, float* C, int accum) {
    GemmDesc& g = g_gd[slot];
    g.active = 1; g.A = A; g.W = W; g.bias = bias;
    g.pre_mode = pre; g.lng = lng; g.lnb = lnb;
    g.epi_act = epi; g.mult = mult; g.residual = residual;
    g.scale = scale; g.C = C; g.accumulate = accum;
}

// Fill an edge slot; returns consumed input node index inn (-2..7)
__device__ int fill_edge(int node, int which, int sel, float w, int lind, int snode,
                         const float* const* bufs,
                         const float* eW, const float* eb, const float* eg, const float* ebe,
                         float* dst) {
    int se = sel / 5, op = sel % 5;
    int inn = (se == 0) ? -2 : (snode + se);
    int e = lind + se;
    const float* src = bufs[inn + 2];
    if (op == 4) {
        CopyDesc& cd = g_cd[node * 3 + which];
        cd.active = 1; cd.src = src; cd.dst = dst; cd.scale = w;
    } else {
        set_gd(node * 7 + which,
               src, eW + (size_t)e * D * D, eb + e * D,
               (op <= 2) ? 1 : 0, eg + e * D, ebe + e * D,
               (op == 0) ? 1 : ((op == 1) ? 2 : 0),
               nullptr, nullptr, w, dst, 0);
    }
    return inn;
}

// ---------------- routing kernel: computes routes + writes all descriptors ----------
__global__ void routing_kernel(const float* inpute, const float* inputo,
                               const float* node_p, const float* edge_p,
                               const float* edge_W, const float* edge_b,
                               const float* edge_g, const float* edge_beta,
                               const float* node_W, const float* node_b,
                               const float* node_g, const float* node_beta) {
    if (threadIdx.x != 0 || blockIdx.x != 0) return;

    const float* bufs[10];
    bufs[0] = inpute; bufs[1] = inputo;
    for (int i = 0; i < 8; i++) bufs[2 + i] = g_outs[i];

    for (int i = 0; i < 56; i++) g_gd[i].active = 0;
    for (int i = 0; i < 24; i++) g_cd[i].active = 0;
    for (int i = 0; i < 8; i++) { g_ed[i].active = 0; g_attn_on[i] = 0; }

    int processed = 0;
    int lind = 0;
    for (int c = 0; c < 8; c++) {
        int nsrc = (c + 2 < 5) ? (c + 2) : 5;
        int snode = c - nsrc;
        int L = nsrc * 5;
        float ep0[25], ep1[25], ep2[25];
        for (int s = 0; s < nsrc; s++)
            for (int j = 0; j < 5; j++) {
                int e = lind + s;
                ep0[s * 5 + j] = edge_p[(0 * NEDGEn + e) * 5 + j];
                ep1[s * 5 + j] = edge_p[(1 * NEDGEn + e) * 5 + j];
                ep2[s * 5 + j] = edge_p[(2 * NEDGEn + e) * 5 + j];
            }
        // node activation argmax + softmax weight
        int nact = 0; float bb = node_p[c * 8];
        for (int i = 1; i < 8; i++) { float x = node_p[c * 8 + i]; if (x > bb) { bb = x; nact = i; } }
        float aw;
        { float sum = 0.f; for (int i = 0; i < 8; i++) sum += expf(node_p[c * 8 + i] - bb);
          aw = expf(node_p[c * 8 + nact] - bb) / sum; }

        // q selection: first 5 masked
        int qsel = 5; float qb = ep0[5];
        for (int i = 6; i < L; i++) if (ep0[i] > qb) { qb = ep0[i]; qsel = i; }
        float wq = selw_masked(ep0, L, 1, qsel);

        int ksel = -1, vsel = -1;
        float wk = 0.f, wv = 0.f;
        int ktype = 0;
        if (nact < 7) {
            int km = (nact > 0) ? 1 : 0;
            int start = km ? 5 : 0;
            ksel = start; float kb = ep1[start];
            for (int i = start + 1; i < L; i++) if (ep1[i] > kb) { kb = ep1[i]; ksel = i; }
            wk = selw_masked(ep1, L, km, ksel);
            ktype = (ksel / 5 == 0) ? -2 : -1;
            if (nact < 5) {
                if (nact == 0 && ktype == -2) {
                    vsel = 0; float vb = ep2[0];
                    for (int i = 1; i < 5; i++) if (ep2[i] > vb) { vb = ep2[i]; vsel = i; }
                    wv = selw_masked(ep2, 5, 0, vsel);
                } else {
                    int vm = km;
                    int vstart = vm ? 5 : 0;
                    vsel = vstart; float vb = ep2[vstart];
                    for (int i = vstart + 1; i < L; i++) if (ep2[i] > vb) { vb = ep2[i]; vsel = i; }
                    wv = selw_masked(ep2, L, vm, vsel);
                }
            }
        }

        // edge descriptors
        float* outc = g_outs[c];
        int inn;
        inn = fill_edge(c, 0, qsel, wq, lind, snode, bufs, edge_W, edge_b, edge_g, edge_beta, g_q);
        processed |= 1 << (inn + 2);
        if (nact < 7) {
            inn = fill_edge(c, 1, ksel, wk, lind, snode, bufs, edge_W, edge_b, edge_g, edge_beta, g_k);
            processed |= 1 << (inn + 2);
        }
        if (nact < 5) {
            inn = fill_edge(c, 2, vsel, wv, lind, snode, bufs, edge_W, edge_b, edge_g, edge_beta, g_v);
            processed |= 1 << (inn + 2);
        }

        // node descriptors
        const float* nw  = node_W + (size_t)c * 4 * D * D;
        const float* nbv = node_b + (size_t)c * 4 * D;
        const float* ngv = node_g + (size_t)c * D;
        const float* nbe = node_beta + (size_t)c * D;
        int s3 = c * 7 + 3, s4 = c * 7 + 4, s5 = c * 7 + 5, s6 = c * 7 + 6;

        if (nact == 0) {
            set_gd(s3, g_q, nw,             nbv,         1, ngv, nbe, 0, nullptr, nullptr, 1.f, g_t1, 0);
            set_gd(s4, g_k, nw + D * D,     nbv + D,     0, nullptr, nullptr, 0, nullptr, nullptr, 1.f, g_t2, 0);
            set_gd(s5, g_v, nw + 2 * D * D, nbv + 2 * D, 0, nullptr, nullptr, 0, nullptr, nullptr, 1.f, g_t3, 0);
            g_attn_on[c] = 1;
            set_gd(s6, g_t4, nw + 3 * D * D, nbv + 3 * D, 0, nullptr, nullptr, 0, nullptr, g_q, aw, outc, 0);
        } else if (nact == 1) {
            set_gd(s3, g_q, nw,         nbv,     0, nullptr, nullptr, 2, nullptr, nullptr, 1.f, g_t1, 0);
            set_gd(s4, g_k, nw + D * D, nbv + D, 0, nullptr, nullptr, 0, g_t1, nullptr, 1.f, g_t4, 0);
            set_gd(s6, g_t4, nw + 3 * D * D, nbv + 3 * D, 0, nullptr, nullptr, 0, nullptr, g_q, aw, outc, 0);
        } else if (nact == 3) {
            set_gd(s3, g_q, nw,             nullptr, 0, nullptr, nullptr, 0, nullptr, nullptr, 1.f, g_t1, 0);
            set_gd(s4, g_k, nw + D * D,     nullptr, 0, nullptr, nullptr, 0, nullptr, nullptr, 1.f, g_t1, 1);
            set_gd(s5, g_v, nw + 2 * D * D, nullptr, 0, nullptr, nullptr, 0, nullptr, nullptr, 1.f, g_t1, 1);
            set_gd(s6, g_t1, nw + 3 * D * D, nbv + 3 * D, 2, nullptr, nullptr, 0, nullptr, g_q, aw, outc, 0);
        } else if (nact == 5) {
            set_gd(s4, g_k, nw + D * D, nbv + D, 0, nullptr, nullptr, 2, nullptr, g_q, aw, outc, 0);
        } else { // 2, 4, 6, 7 elementwise
            ElemDesc& e = g_ed[c];
            e.active = 1; e.opcode = nact;
            e.q = g_q; e.k = g_k; e.v = g_v;
            e.g = ngv; e.b = nbe; e.scale = aw; e.dst = outc;
        }
        lind += nsrc;
    }
    int rem = 0;
    for (int n = 0; n < 8; n++)
        if (!((processed >> (n + 2)) & 1)) rem |= 1 << n;
    g_rem_mask = rem;
}

// ---------------- conv_slot: pre-split A (pre-op fused) and W to bf16 hi/lo -------
// blocks 0..511: A rows (8 rows/block, one warp per row)
// blocks 512..639: W rows (4 k-rows/block)
__global__ __launch_bounds__(256) void conv_slot(int slot) {
    GemmDesc d = g_gd[slot];
    if (!d.active) return;
    int b = blockIdx.x, tid = threadIdx.x;

    if (b < 512) {
        int r = b * 8 + (tid >> 5);
        int lane = tid & 31;
        const float* src = d.A + (size_t)r * D + lane * 16;
        float x[16];
        #pragma unroll
        for (int i = 0; i < 4; i++) {
            float4 v = *(const float4*)(src + i * 4);
            x[i * 4 + 0] = v.x; x[i * 4 + 1] = v.y;
            x[i * 4 + 2] = v.z; x[i * 4 + 3] = v.w;
        }
        if (d.pre_mode == 1) {
            float s = 0.f, q = 0.f;
            #pragma unroll
            for (int i = 0; i < 16; i++) { s += x[i]; q += x[i] * x[i]; }
            #pragma unroll
            for (int off = 16; off > 0; off >>= 1) {
                s += __shfl_xor_sync(0xFFFFFFFFu, s, off);
                q += __shfl_xor_sync(0xFFFFFFFFu, q, off);
            }
            float mean = s * (1.f / 512.f);
            float var = q * (1.f / 512.f) - mean * mean;
            float rstd = rsqrtf(var + EPSf);
            #pragma unroll
            for (int i = 0; i < 16; i++) {
                int j = lane * 16 + i;
                x[i] = (x[i] - mean) * rstd * d.lng[j] + d.lnb[j];
            }
        } else if (d.pre_mode == 2) {
            #pragma unroll
            for (int i = 0; i < 16; i++) x[i] = fmaxf(x[i], 0.f);
        }
        uint2 o[8];
        #pragma unroll
        for (int i = 0; i < 8; i++) o[i] = split_pair(x[2 * i], x[2 * i + 1]);
        size_t base = (size_t)r * 64 + lane * 2;
        g_Ahi4[base + 0] = make_uint4(o[0].x, o[1].x, o[2].x, o[3].x);
        g_Ahi4[base + 1] = make_uint4(o[4].x, o[5].x, o[6].x, o[7].x);
        g_Alo4[base + 0] = make_uint4(o[0].y, o[1].y, o[2].y, o[3].y);
        g_Alo4[base + 1] = make_uint4(o[4].y, o[5].y, o[6].y, o[7].y);
    } else {
        int r = (b - 512) * 4 + (tid >> 6);
        int cq = tid & 63;                       // 8-col chunk
        const float* src = d.W + (size_t)r * D + cq * 8;
        float4 v0 = *(const float4*)src;
        float4 v1 = *(const float4*)(src + 4);
        uint2 o0 = split_pair(v0.x, v0.y);
        uint2 o1 = split_pair(v0.z, v0.w);
        uint2 o2 = split_pair(v1.x, v1.y);
        uint2 o3 = split_pair(v1.z, v1.w);
        size_t idx = (size_t)r * 64 + cq;
        g_Whi4[idx] = make_uint4(o0.x, o1.x, o2.x, o3.x);
        g_Wlo4[idx] = make_uint4(o0.y, o1.y, o2.y, o3.y);
    }
}

// ---------------- GEMM slot kernel: pre-split bf16, ldmatrix + swizzled tiles -----
// C[NTOK,D] = epi( preA[NTOK,D] @ W[D,D] + bias ) (*mult)(+residual)(*scale)
// BM=128, BN=64, BK=32; 8 warps 4(M)x2(N); warp tile 32x32 = 2 m16 x 4 n8.
// A tiles: [128 rows][4 chunks], chunk swizzle c^((row>>1)&3)
// B tiles: [32 k rows][8 chunks], chunk swizzle c^(krow&7)
__global__ __launch_bounds__(256) void gemm_slot(int slot) {
    GemmDesc d = g_gd[slot];
    if (!d.active) return;

    __shared__ uint4 sAhi[128 * 4], sAlo[128 * 4];
    __shared__ uint4 sBhi[32 * 8], sBlo[32 * 8];

    uint32_t aHiB = (uint32_t)__cvta_generic_to_shared(sAhi);
    uint32_t aLoB = (uint32_t)__cvta_generic_to_shared(sAlo);
    uint32_t bHiB = (uint32_t)__cvta_generic_to_shared(sBhi);
    uint32_t bLoB = (uint32_t)__cvta_generic_to_shared(sBlo);

    int tid = threadIdx.x;
    int m0 = blockIdx.y * BM;
    int n0 = blockIdx.x * BN;

    int warp = tid >> 5, lane = tid & 31;
    int g = lane >> 2, t = lane & 3;
    int wM = (warp >> 1) * 32;    // 4 warps along M
    int wN = (warp & 1) * 32;     // 2 warps along N

    // staging maps
    int arow = tid >> 1;           // A row 0..127
    int ac0 = (tid & 1) * 2;       // A chunk base {0,2}
    int bk = tid >> 3;             // B k row 0..31
    int bc = tid & 7;              // B chunk 0..7
    int asw = (arow >> 1) & 3;
    int nq8 = n0 >> 3;             // W chunk col base

    float acc[2][4][4];
    #pragma unroll
    for (int a = 0; a < 2; a++)
        #pragma unroll
        for (int bb = 0; bb < 4; bb++)
            #pragma unroll
            for (int cc = 0; cc < 4; cc++) acc[a][bb][cc] = 0.f;

    uint4 rah[2], ral[2], rbh, rbl;
    {
        size_t abase = (size_t)(m0 + arow) * 64 + ac0;
        rah[0] = g_Ahi4[abase]; rah[1] = g_Ahi4[abase + 1];
        ral[0] = g_Alo4[abase]; ral[1] = g_Alo4[abase + 1];
        size_t wbase = (size_t)bk * 64 + nq8 + bc;
        rbh = g_Whi4[wbase]; rbl = g_Wlo4[wbase];
    }

    for (int kt = 0; kt < D / BK; kt++) {
        // ---- stage (pure copies with swizzle) ----
        sAhi[arow * 4 + ((ac0 + 0) ^ asw)] = rah[0];
        sAhi[arow * 4 + ((ac0 + 1) ^ asw)] = rah[1];
        sAlo[arow * 4 + ((ac0 + 0) ^ asw)] = ral[0];
        sAlo[arow * 4 + ((ac0 + 1) ^ asw)] = ral[1];
        sBhi[bk * 8 + (bc ^ (bk & 7))] = rbh;
        sBlo[bk * 8 + (bc ^ (bk & 7))] = rbl;
        __syncthreads();
        // ---- prefetch next stage ----
        if (kt + 1 < D / BK) {
            size_t abase = (size_t)(m0 + arow) * 64 + (kt + 1) * 4 + ac0;
            rah[0] = g_Ahi4[abase]; rah[1] = g_Ahi4[abase + 1];
            ral[0] = g_Alo4[abase]; ral[1] = g_Alo4[abase + 1];
            size_t wbase = (size_t)((kt + 1) * 32 + bk) * 64 + nq8 + bc;
            rbh = g_Whi4[wbase]; rbl = g_Wlo4[wbase];
        }
        // ---- compute: 2 k16 steps ----
        #pragma unroll
        for (int kb = 0; kb < 2; kb++) {
            uint32_t ahi[2][4], alo[2][4];
            #pragma unroll
            for (int mt = 0; mt < 2; mt++) {
                int row = wM + mt * 16 + (lane & 15);
                int c = kb * 2 + (lane >> 4);
                uint32_t off = (uint32_t)(row * 4 + (c ^ ((row >> 1) & 3))) * 16;
                ldsm_x4(ahi[mt], aHiB + off);
                ldsm_x4(alo[mt], aLoB + off);
            }
            uint32_t bh[4][2], bl[4][2];
            #pragma unroll
            for (int ng = 0; ng < 2; ng++) {
                int krow = kb * 16 + 8 * ((lane >> 3) & 1) + (lane & 7);
                int nch = (wN + ng * 16 + 8 * (lane >> 4)) >> 3;
                uint32_t off = (uint32_t)krow * 128 + (uint32_t)((nch ^ (krow & 7)) << 4);
                uint32_t r[4];
                ldsm_x4_trans(r, bHiB + off);
                bh[ng * 2][0] = r[0]; bh[ng * 2][1] = r[1];
                bh[ng * 2 + 1][0] = r[2]; bh[ng * 2 + 1][1] = r[3];
                ldsm_x4_trans(r, bLoB + off);
                bl[ng * 2][0] = r[0]; bl[ng * 2][1] = r[1];
                bl[ng * 2 + 1][0] = r[2]; bl[ng * 2 + 1][1] = r[3];
            }
            #pragma unroll
            for (int mt = 0; mt < 2; mt++)
                #pragma unroll
                for (int nt = 0; nt < 4; nt++) {
                    mma_bf16(acc[mt][nt], ahi[mt], bh[nt]);
                    mma_bf16(acc[mt][nt], ahi[mt], bl[nt]);
                    mma_bf16(acc[mt][nt], alo[mt], bh[nt]);
                }
        }
        __syncthreads();
    }

    // epilogue
    #pragma unroll
    for (int mt = 0; mt < 2; mt++)
        #pragma unroll
        for (int nt = 0; nt < 4; nt++) {
            int m = m0 + wM + mt * 16 + g;
            int n = n0 + wN + nt * 8 + 2 * t;
            float b0v = 0.f, b1v = 0.f;
            if (d.bias) { b0v = d.bias[n]; b1v = d.bias[n + 1]; }
            #pragma unroll
            for (int rr = 0; rr < 2; rr++) {
                int mr = m + rr * 8;
                float x0 = acc[mt][nt][rr * 2 + 0] + b0v;
                float x1 = acc[mt][nt][rr * 2 + 1] + b1v;
                if (d.epi_act == 1) { x0 = fmaxf(x0, 0.f); x1 = fmaxf(x1, 0.f); }
                else if (d.epi_act == 2) { x0 = gelu_f(x0); x1 = gelu_f(x1); }
                if (d.mult) {
                    float2 mv = *(const float2*)(d.mult + (size_t)mr * D + n);
                    x0 *= mv.x; x1 *= mv.y;
                }
                if (d.residual) {
                    float2 rv = *(const float2*)(d.residual + (size_t)mr * D + n);
                    x0 += rv.x; x1 += rv.y;
                }
                x0 *= d.scale; x1 *= d.scale;
                if (d.accumulate) {
                    float2 cv = *(const float2*)(d.C + (size_t)mr * D + n);
                    x0 += cv.x; x1 += cv.y;
                }
                *(float2*)(d.C + (size_t)mr * D + n) = make_float2(x0, x1);
            }
        }
}

// ---------------- edge op4 copy-scale ----------------
__global__ void copy_slot(int slot) {
    CopyDesc d = g_cd[slot];
    if (!d.active) return;
    int i = blockIdx.x * blockDim.x + threadIdx.x;
    int stride = gridDim.x * blockDim.x;
    const float4* src = (const float4*)d.src;
    float4* dst = (float4*)d.dst;
    for (; i < NTOK * D / 4; i += stride) {
        float4 v = src[i];
        v.x *= d.scale; v.y *= d.scale; v.z *= d.scale; v.w *= d.scale;
        dst[i] = v;
    }
}

// ---------------- attention (act 0): one warp per query row, online softmax ------
__global__ __launch_bounds__(256) void attn_slot(int c) {
    if (!g_attn_on[c]) return;
    int warp = threadIdx.x >> 5, lane = threadIdx.x & 31;
    int bh = blockIdx.x;            // 0..31
    int b = bh >> 3, h = bh & 7;
    int s = blockIdx.y * 8 + warp;  // 0..1023

    const float* qrow = g_t1 + (size_t)((b << 10) + s) * D + h * 64 + lane * 2;
    float q0 = qrow[0], q1 = qrow[1];
    const float* kbase = g_t2 + (size_t)(b << 10) * D + h * 64 + lane * 2;
    const float* vbase = g_t3 + (size_t)(b << 10) * D + h * 64 + lane * 2;

    float m = -1e30f, l = 0.f, a0 = 0.f, a1 = 0.f;
    for (int sk = 0; sk < 1024; sk++) {
        float2 kk = *(const float2*)(kbase + (size_t)sk * D);
        float p = q0 * kk.x + q1 * kk.y;
        p += __shfl_xor_sync(0xFFFFFFFFu, p, 16);
        p += __shfl_xor_sync(0xFFFFFFFFu, p, 8);
        p += __shfl_xor_sync(0xFFFFFFFFu, p, 4);
        p += __shfl_xor_sync(0xFFFFFFFFu, p, 2);
        p += __shfl_xor_sync(0xFFFFFFFFu, p, 1);
        float dot = p * 0.125f;
        float mn = fmaxf(m, dot);
        float corr = __expf(m - mn);
        float w = __expf(dot - mn);
        float2 vv = *(const float2*)(vbase + (size_t)sk * D);
        l = l * corr + w;
        a0 = a0 * corr + w * vv.x;
        a1 = a1 * corr + w * vv.y;
        m = mn;
    }
    float inv = 1.f / l;
    float* orow = g_t4 + (size_t)((b << 10) + s) * D + h * 64 + lane * 2;
    orow[0] = a0 * inv;
    orow[1] = a1 * inv;
}

// ---------------- elementwise node ops (acts 2,4,6,7) ----------------
__global__ __launch_bounds__(256) void elem_node_kernel(int c) {
    ElemDesc d = g_ed[c];
    if (!d.active) return;
    int row = blockIdx.x;
    int tid = threadIdx.x;
    size_t base = (size_t)row * D;
    float x[2];
    #pragma unroll
    for (int i = 0; i < 2; i++) {
        int j = tid + i * 256;
        float qv = d.q[base + j];
        if (d.opcode == 2) x[i] = qv + d.k[base + j] + d.v[base + j];
        else if (d.opcode == 4) {
            float kv = d.k[base + j];
            x[i] = qv * (1.f / (1.f + expf(-kv))) + d.v[base + j];
        }
        else if (d.opcode == 6) x[i] = qv + d.k[base + j];
        else x[i] = qv; // 7
    }
    if (d.opcode == 2 || d.opcode == 7) {
        __shared__ float rs[256], rq[256];
        rs[tid] = x[0] + x[1];
        rq[tid] = x[0] * x[0] + x[1] * x[1];
        __syncthreads();
        for (int off = 128; off > 0; off >>= 1) {
            if (tid < off) { rs[tid] += rs[tid + off]; rq[tid] += rq[tid + off]; }
            __syncthreads();
        }
        float mean = rs[0] * (1.f / 512.f);
        float var = rq[0] * (1.f / 512.f) - mean * mean;
        float rstd = rsqrtf(var + EPSf);
        #pragma unroll
        for (int i = 0; i < 2; i++) {
            int j = tid + i * 256;
            d.dst[base + j] = d.scale * ((x[i] - mean) * rstd * d.g[j] + d.b[j]);
        }
    } else {
        #pragma unroll
        for (int i = 0; i < 2; i++) {
            int j = tid + i * 256;
            d.dst[base + j] = d.scale * x[i];
        }
    }
}

// ---------------- final: sum remaining outs + LayerNorm ----------------
__global__ __launch_bounds__(256) void final_kernel(const float* out_g, const float* out_beta,
                                                    float* out) {
    int row = blockIdx.x;
    int tid = threadIdx.x;
    int mask = g_rem_mask;
    size_t base = (size_t)row * D;
    float x[2];
    #pragma unroll
    for (int i = 0; i < 2; i++) {
        int j = tid + i * 256;
        float s = 0.f;
        for (int n = 0; n < 8; n++)
            if ((mask >> n) & 1) s += g_outs[n][base + j];
        x[i] = s;
    }
    __shared__ float rs[256], rq[256];
    rs[tid] = x[0] + x[1];
    rq[tid] = x[0] * x[0] + x[1] * x[1];
    __syncthreads();
    for (int off = 128; off > 0; off >>= 1) {
        if (tid < off) { rs[tid] += rs[tid + off]; rq[tid] += rq[tid + off]; }
        __syncthreads();
    }
    float mean = rs[0] * (1.f / 512.f);
    float var = rq[0] * (1.f / 512.f) - mean * mean;
    float rstd = rsqrtf(var + EPSf);
    #pragma unroll
    for (int i = 0; i < 2; i++) {
        int j = tid + i * 256;
        out[base + j] = (x[i] - mean) * rstd * out_g[j] + out_beta[j];
    }
}

// ---------------- launch ----------------
extern "C" void kernel_launch(void* const* d_in, const int* in_sizes, int n_in,
                              void* d_out, int out_size) {
    const float* inpute   = (const float*)d_in[0];
    const float* inputo   = (const float*)d_in[1];
    const float* node_p   = (const float*)d_in[2];
    const float* edge_p   = (const float*)d_in[3];
    const float* edge_W   = (const float*)d_in[4];
    const float* edge_b   = (const float*)d_in[5];
    const float* edge_g   = (const float*)d_in[6];
    const float* edge_bet = (const float*)d_in[7];
    const float* node_W   = (const float*)d_in[8];
    const float* node_b   = (const float*)d_in[9];
    const float* node_g   = (const float*)d_in[10];
    const float* node_bet = (const float*)d_in[11];
    const float* out_g    = (const float*)d_in[12];
    const float* out_bet  = (const float*)d_in[13];
    float* out = (float*)d_out;

    routing_kernel<<<1, 1>>>(inpute, inputo, node_p, edge_p,
                             edge_W, edge_b, edge_g, edge_bet,
                             node_W, node_b, node_g, node_bet);

    dim3 ggrid(D / BN, NTOK / BM);   // (8, 32)
    for (int c = 0; c < 8; c++) {
        for (int w = 0; w < 3; w++) {
            conv_slot<<<640, 256>>>(c * 7 + w);
            gemm_slot<<<ggrid, 256>>>(c * 7 + w);
            copy_slot<<<512, 256>>>(c * 3 + w);
        }
        for (int w = 3; w < 6; w++) {
            conv_slot<<<640, 256>>>(c * 7 + w);
            gemm_slot<<<ggrid, 256>>>(c * 7 + w);
        }
        attn_slot<<<dim3(32, 128), 256>>>(c);
        conv_slot<<<640, 256>>>(c * 7 + 6);
        gemm_slot<<<ggrid, 256>>>(c * 7 + 6);
        elem_node_kernel<<<NTOK, 256>>>(c);
    }
    final_kernel<<<NTOK, 256>>>(out_g, out_bet, out);
}